// round 11
// baseline (speedup 1.0000x reference)
#include <cuda_runtime.h>
#include <cstdint>

#define N_NODES 50000
#define N_EDGES 600000
#define N_GRAPHS 512
#define DIM 128
#define N_FEAT 78
#define N_LAYERS 4
#define BN_EPS 1e-5f

typedef unsigned long long ull;

// ---------------- scratch (device globals; no allocation allowed) ----------
__device__ float g_u[2][(size_t)N_NODES * DIM];  // ping-pong node features
__device__ float g_z[(size_t)N_NODES * DIM];     // gathered GIN input
__device__ float g_acc[(size_t)N_NODES * DIM];   // layer-conv accumulator
__device__ float g_stats[2][2 * DIM];            // double-buffered BN sums
__device__ int   g_deg[N_NODES];
__device__ int   g_ptr[N_NODES + 1];
__device__ int   g_cur[N_NODES];
__device__ int   g_csr[N_EDGES];                 // src sorted by dst

// ---------------- f32x2 packed-FMA helpers (FFMA2) -------------------------
__device__ __forceinline__ void fma2(ull& d, ull a, ull b) {
    asm("fma.rn.f32x2 %0, %1, %2, %0;" : "+l"(d) : "l"(a), "l"(b));
}
__device__ __forceinline__ ull bcast2(float x) {
    unsigned u = __float_as_uint(x);
    ull r; asm("mov.b64 %0, {%1, %1};" : "=l"(r) : "r"(u)); return r;
}
__device__ __forceinline__ ull pack2(float x, float y) {
    ull r; asm("mov.b64 %0, {%1, %2};" : "=l"(r)
               : "r"(__float_as_uint(x)), "r"(__float_as_uint(y))); return r;
}
__device__ __forceinline__ float2 unpack2(ull v) {
    unsigned lo, hi;
    asm("mov.b64 {%0, %1}, %2;" : "=r"(lo), "=r"(hi) : "l"(v));
    return make_float2(__uint_as_float(lo), __uint_as_float(hi));
}

// ---------------- 64-row GEMM micro-kernel, 8x8 thread tile ----------------
// 128 threads: ty = tid>>4 (8 row groups of 8), tx = tid&15 (8-col groups).
// sA pre-offset to the K-slice start; sW holds KSTEPS rows of W.
template <int KSTEPS, int APAD>
__device__ __forceinline__ void mma8(const float* __restrict__ sA,
                                     const float* __restrict__ sW,
                                     ull acc[8][4], int ty, int c0) {
    #pragma unroll 2
    for (int kk = 0; kk < KSTEPS; kk += 4) {
        float a[8][4];
        #pragma unroll
        for (int i = 0; i < 8; i++)
            *(float4*)a[i] = *(const float4*)&sA[(ty * 8 + i) * APAD + kk];
        #pragma unroll
        for (int k = 0; k < 4; k++) {
            const ulonglong2* wp = (const ulonglong2*)&sW[(kk + k) * DIM + c0];
            ulonglong2 w01 = wp[0], w23 = wp[1];
            #pragma unroll
            for (int i = 0; i < 8; i++) {
                ull av = bcast2(a[i][k]);
                fma2(acc[i][0], av, w01.x); fma2(acc[i][1], av, w01.y);
                fma2(acc[i][2], av, w23.x); fma2(acc[i][3], av, w23.y);
            }
        }
    }
}

#define ZPAD 132
#define XPAD 80
#define NT 128

// gin smem: W quarter (32x128) + Z tile (64xZPAD) -> 4 blocks/SM
#define GIN_WQ   (32 * DIM)                       // 4096 floats
#define SMEM_GIN ((GIN_WQ + 64 * ZPAD) * (int)sizeof(float))   // 50176 B
// ini smem: W buf (40x128 max) + X tile (64xXPAD) + T tile (64xZPAD)
#define INI_WH   (40 * DIM)                       // 5120 floats
#define INI_X    (64 * XPAD)                      // 5120 floats
#define SMEM_INI ((INI_WH + INI_X + 64 * ZPAD) * (int)sizeof(float)) // 74752 B

// ---------------- CSR build --------------------------------------------------
__global__ void init_kernel(float* __restrict__ out) {
    int i = blockIdx.x * blockDim.x + threadIdx.x;
    if (i < N_NODES) g_deg[i] = 0;
    if (i < N_GRAPHS * DIM) out[i] = 0.0f;
}

__global__ void count_kernel(const int* __restrict__ ei) {
    int e = blockIdx.x * blockDim.x + threadIdx.x;
    if (e < N_EDGES) atomicAdd(&g_deg[__ldg(&ei[N_EDGES + e])], 1);
}

__global__ void scan_kernel() {
    __shared__ int ssum[1024];
    const int t = threadIdx.x;
    const int CH = (N_NODES + 1023) / 1024;   // 49
    const int base = t * CH;
    int sum = 0;
    for (int i = 0; i < CH; i++) {
        int idx = base + i;
        if (idx < N_NODES) sum += g_deg[idx];
    }
    ssum[t] = sum;
    __syncthreads();
    for (int off = 1; off < 1024; off <<= 1) {
        int v = (t >= off) ? ssum[t - off] : 0;
        __syncthreads();
        ssum[t] += v;
        __syncthreads();
    }
    int run = ssum[t] - sum;
    for (int i = 0; i < CH; i++) {
        int idx = base + i;
        if (idx < N_NODES) {
            g_ptr[idx] = run;
            g_cur[idx] = run;
            run += g_deg[idx];
        }
    }
    if (t == 0) g_ptr[N_NODES] = N_EDGES;
}

__global__ void fill_kernel(const int* __restrict__ ei) {
    int e = blockIdx.x * blockDim.x + threadIdx.x;
    if (e >= N_EDGES) return;
    int dst = __ldg(&ei[N_EDGES + e]);
    int pos = atomicAdd(&g_cur[dst], 1);
    g_csr[pos] = __ldg(&ei[e]);
}

// ---------------- ini embed: u0 = relu(x@W1+b1)@W2+b2 ----------------------
__global__ void __launch_bounds__(NT, 3)
ini_gemm_kernel(const float* __restrict__ x,
                const float* __restrict__ w1, const float* __restrict__ b1,
                const float* __restrict__ w2, const float* __restrict__ b2) {
    extern __shared__ float sm[];
    float* sW = sm;                  // 5120 floats: W slice
    float* sX = sm + INI_WH;         // 5120 floats: X tile (64 x XPAD)
    float* sT = sX + INI_X;          // 8448 floats: T tile (64 x ZPAD)
    const int tid = threadIdx.x;
    const int rbase = blockIdx.x * 64;

    for (int i = tid; i < 64 * XPAD; i += NT) {
        int r = i / XPAD, c = i - r * XPAD;
        sX[i] = (c < N_FEAT && rbase + r < N_NODES)
                ? x[(size_t)(rbase + r) * N_FEAT + c] : 0.0f;
    }

    const int ty = tid >> 4, tx = tid & 15, c0 = tx << 3;
    ull acc[8][4];

    // ---- stage 1: T = relu(x @ W1 + b1), 2 half-passes of 40 k-rows ----
    {
        ull b[4];
        #pragma unroll
        for (int j = 0; j < 4; j++)
            b[j] = pack2(b1[c0 + 2 * j], b1[c0 + 2 * j + 1]);
        #pragma unroll
        for (int i = 0; i < 8; i++)
            #pragma unroll
            for (int j = 0; j < 4; j++) acc[i][j] = b[j];
    }
    #pragma unroll 1
    for (int h = 0; h < 2; h++) {
        __syncthreads();           // sW free (and X tile ready for h=0)
        for (int i = tid * 4; i < 40 * DIM; i += NT * 4) {
            int gk = h * 40 * DIM + i;
            float4 v = make_float4(0, 0, 0, 0);
            if (gk < N_FEAT * DIM) v = *(const float4*)&w1[gk];
            *(float4*)&sW[i] = v;  // zero-fill padded k rows 78,79
        }
        __syncthreads();
        mma8<40, XPAD>(sX + h * 40, sW, acc, ty, c0);
    }
    __syncthreads();               // all stage-1 reads done

    #pragma unroll
    for (int i = 0; i < 8; i++)
        #pragma unroll
        for (int j = 0; j < 4; j++) {
            float2 f = unpack2(acc[i][j]);
            sT[(ty * 8 + i) * ZPAD + c0 + 2 * j]     = fmaxf(f.x, 0.0f);
            sT[(ty * 8 + i) * ZPAD + c0 + 2 * j + 1] = fmaxf(f.y, 0.0f);
        }

    // ---- stage 2: U = T @ W2 + b2, 4 quarter-passes of 32 k-rows ----
    {
        ull b[4];
        #pragma unroll
        for (int j = 0; j < 4; j++)
            b[j] = pack2(b2[c0 + 2 * j], b2[c0 + 2 * j + 1]);
        #pragma unroll
        for (int i = 0; i < 8; i++)
            #pragma unroll
            for (int j = 0; j < 4; j++) acc[i][j] = b[j];
    }
    #pragma unroll 1
    for (int q = 0; q < 4; q++) {
        __syncthreads();           // T writes visible (q=0); prev reads done
        for (int i = tid * 4; i < 32 * DIM; i += NT * 4)
            *(float4*)&sW[i] = *(const float4*)&w2[q * 32 * DIM + i];
        __syncthreads();
        mma8<32, ZPAD>(sT + q * 32, sW, acc, ty, c0);
    }

    #pragma unroll
    for (int i = 0; i < 8; i++) {
        int r = rbase + ty * 8 + i;
        if (r < N_NODES) {
            float2 f0 = unpack2(acc[i][0]), f1 = unpack2(acc[i][1]);
            float2 f2 = unpack2(acc[i][2]), f3 = unpack2(acc[i][3]);
            *(float4*)&g_u[0][(size_t)r * DIM + c0] =
                make_float4(f0.x, f0.y, f1.x, f1.y);
            *(float4*)&g_u[0][(size_t)r * DIM + c0 + 4] =
                make_float4(f2.x, f2.y, f3.x, f3.y);
        }
    }
}

// ---------------- gather: z = sc*(u+sum u_src)+(deg+1)*sh; acc += lw*h -----
// 1 warp per node; BN coefficients computed inline from prev-layer stats.
// Block 0 zeroes the stats buffer the following gemm will accumulate into.
__global__ void __launch_bounds__(256)
gather_kernel(const float* __restrict__ gamma, const float* __restrict__ beta,
              const float* __restrict__ lwp, const float* __restrict__ lbp,
              int layer, int rd) {
    if (blockIdx.x == 0 && threadIdx.x < 2 * DIM)
        g_stats[(layer + 1) & 1][threadIdx.x] = 0.0f;
    int node = (blockIdx.x * blockDim.x + threadIdx.x) >> 5;
    if (node >= N_NODES) return;
    const float* __restrict__ uin = g_u[rd];
    const int lane = threadIdx.x & 31, cc = lane << 2;

    float4 scv = make_float4(1, 1, 1, 1), shv = make_float4(0, 0, 0, 0);
    if (layer > 0) {
        const float* st = g_stats[layer & 1];
        float sc[4], sh[4];
        #pragma unroll
        for (int j = 0; j < 4; j++) {
            float mean = __ldg(&st[cc + j]) * (1.0f / N_NODES);
            float var  = __ldg(&st[DIM + cc + j]) * (1.0f / N_NODES)
                         - mean * mean;
            sc[j] = rsqrtf(var + BN_EPS) * __ldg(&gamma[cc + j]);
            sh[j] = __ldg(&beta[cc + j]) - mean * sc[j];
        }
        scv = make_float4(sc[0], sc[1], sc[2], sc[3]);
        shv = make_float4(sh[0], sh[1], sh[2], sh[3]);
    }

    float4 un = *(const float4*)&uin[(size_t)node * DIM + cc];
    int p0 = __ldg(&g_ptr[node]), p1 = __ldg(&g_ptr[node + 1]);
    float4 s0 = un, s1 = make_float4(0, 0, 0, 0);
    float4 s2 = make_float4(0, 0, 0, 0), s3 = make_float4(0, 0, 0, 0);
    int k = p0;
    for (; k + 4 <= p1; k += 4) {
        int sa = __ldg(&g_csr[k]),      sb = __ldg(&g_csr[k + 1]);
        int sc2 = __ldg(&g_csr[k + 2]), sd = __ldg(&g_csr[k + 3]);
        float4 ua = *(const float4*)&uin[(size_t)sa * DIM + cc];
        float4 ub = *(const float4*)&uin[(size_t)sb * DIM + cc];
        float4 uc = *(const float4*)&uin[(size_t)sc2 * DIM + cc];
        float4 ud = *(const float4*)&uin[(size_t)sd * DIM + cc];
        s0.x += ua.x; s0.y += ua.y; s0.z += ua.z; s0.w += ua.w;
        s1.x += ub.x; s1.y += ub.y; s1.z += ub.z; s1.w += ub.w;
        s2.x += uc.x; s2.y += uc.y; s2.z += uc.z; s2.w += uc.w;
        s3.x += ud.x; s3.y += ud.y; s3.z += ud.z; s3.w += ud.w;
    }
    for (; k < p1; k++) {
        int sa = __ldg(&g_csr[k]);
        float4 ua = *(const float4*)&uin[(size_t)sa * DIM + cc];
        s0.x += ua.x; s0.y += ua.y; s0.z += ua.z; s0.w += ua.w;
    }
    s0.x += s1.x + s2.x + s3.x; s0.y += s1.y + s2.y + s3.y;
    s0.z += s1.z + s2.z + s3.z; s0.w += s1.w + s2.w + s3.w;
    float dp1 = (float)(p1 - p0 + 1);
    float4 z4;
    z4.x = fmaf(scv.x, s0.x, dp1 * shv.x);
    z4.y = fmaf(scv.y, s0.y, dp1 * shv.y);
    z4.z = fmaf(scv.z, s0.z, dp1 * shv.z);
    z4.w = fmaf(scv.w, s0.w, dp1 * shv.w);
    *(float4*)&g_z[(size_t)node * DIM + cc] = z4;

    if (layer > 0) {
        const float lw_prev = __ldg(&lwp[layer - 1]);
        float4 h;
        h.x = fmaf(un.x, scv.x, shv.x); h.y = fmaf(un.y, scv.y, shv.y);
        h.z = fmaf(un.z, scv.z, shv.z); h.w = fmaf(un.w, scv.w, shv.w);
        float4 a;
        if (layer == 1) {
            float lb = __ldg(lbp);
            a = make_float4(lb, lb, lb, lb);
        } else {
            a = *(const float4*)&g_acc[(size_t)node * DIM + cc];
        }
        a.x = fmaf(lw_prev, h.x, a.x); a.y = fmaf(lw_prev, h.y, a.y);
        a.z = fmaf(lw_prev, h.z, a.z); a.w = fmaf(lw_prev, h.w, a.w);
        *(float4*)&g_acc[(size_t)node * DIM + cc] = a;
    }
}

// ---------------- GIN MLP: u_next = relu(relu(z@W1+b1)@W2+b2) + stats ------
// W loaded in quarters (32 rows) -> 49 KB smem -> 4 blocks/SM, 16 warps.
__global__ void __launch_bounds__(NT, 4)
gin_gemm_kernel(const float* __restrict__ w1, const float* __restrict__ b1,
                const float* __restrict__ w2, const float* __restrict__ b2,
                int rd, int sout) {
    extern __shared__ float sm[];
    float* sW = sm;                  // 4096 floats: W quarter (32 rows)
    float* sZ = sm + GIN_WQ;         // 8448 floats: Z / T / stats partials
    const int tid = threadIdx.x;
    const int rbase = blockIdx.x * 64;
    float* __restrict__ uout = g_u[rd ^ 1];
    float* __restrict__ stats = g_stats[sout];

    // coalesced z tile load: 64 rows x 128 cols
    for (int i = tid; i < 64 * 32; i += NT) {
        int r = i >> 5, c4 = (i & 31) << 2;
        int node = rbase + r;
        float4 z = make_float4(0, 0, 0, 0);
        if (node < N_NODES)
            z = *(const float4*)&g_z[(size_t)node * DIM + c4];
        *(float4*)&sZ[r * ZPAD + c4] = z;
    }

    const int ty = tid >> 4, tx = tid & 15, c0 = tx << 3;
    ull acc[8][4];

    // ---- stage 1: T = relu(z @ W1 + b1), 4 quarter-passes ----
    {
        ull b[4];
        #pragma unroll
        for (int j = 0; j < 4; j++)
            b[j] = pack2(b1[c0 + 2 * j], b1[c0 + 2 * j + 1]);
        #pragma unroll
        for (int i = 0; i < 8; i++)
            #pragma unroll
            for (int j = 0; j < 4; j++) acc[i][j] = b[j];
    }
    #pragma unroll 1
    for (int q = 0; q < 4; q++) {
        __syncthreads();           // Z tile ready (q=0) / sW free
        for (int i = tid * 4; i < 32 * DIM; i += NT * 4)
            *(float4*)&sW[i] = *(const float4*)&w1[q * 32 * DIM + i];
        __syncthreads();
        mma8<32, ZPAD>(sZ + q * 32, sW, acc, ty, c0);
    }
    __syncthreads();               // all stage-1 reads of sZ/sW done

    #pragma unroll
    for (int i = 0; i < 8; i++)
        #pragma unroll
        for (int j = 0; j < 4; j++) {
            float2 f = unpack2(acc[i][j]);
            sZ[(ty * 8 + i) * ZPAD + c0 + 2 * j]     = fmaxf(f.x, 0.0f);
            sZ[(ty * 8 + i) * ZPAD + c0 + 2 * j + 1] = fmaxf(f.y, 0.0f);
        }

    // ---- stage 2: u_next = relu(T @ W2 + b2), 4 quarter-passes ----
    {
        ull b[4];
        #pragma unroll
        for (int j = 0; j < 4; j++)
            b[j] = pack2(b2[c0 + 2 * j], b2[c0 + 2 * j + 1]);
        #pragma unroll
        for (int i = 0; i < 8; i++)
            #pragma unroll
            for (int j = 0; j < 4; j++) acc[i][j] = b[j];
    }
    #pragma unroll 1
    for (int q = 0; q < 4; q++) {
        __syncthreads();           // T writes visible / prev reads done
        for (int i = tid * 4; i < 32 * DIM; i += NT * 4)
            *(float4*)&sW[i] = *(const float4*)&w2[q * 32 * DIM + i];
        __syncthreads();
        mma8<32, ZPAD>(sZ + q * 32, sW, acc, ty, c0);
    }
    __syncthreads();               // sZ reads done; reuse for stats partials

    float csum[8], csum2[8];
    #pragma unroll
    for (int j = 0; j < 8; j++) { csum[j] = 0.0f; csum2[j] = 0.0f; }
    #pragma unroll
    for (int i = 0; i < 8; i++) {
        int r = rbase + ty * 8 + i;
        float2 f0 = unpack2(acc[i][0]), f1 = unpack2(acc[i][1]);
        float2 f2 = unpack2(acc[i][2]), f3 = unpack2(acc[i][3]);
        float o[8] = { fmaxf(f0.x, 0.f), fmaxf(f0.y, 0.f),
                       fmaxf(f1.x, 0.f), fmaxf(f1.y, 0.f),
                       fmaxf(f2.x, 0.f), fmaxf(f2.y, 0.f),
                       fmaxf(f3.x, 0.f), fmaxf(f3.y, 0.f) };
        if (r < N_NODES) {
            *(float4*)&uout[(size_t)r * DIM + c0] =
                make_float4(o[0], o[1], o[2], o[3]);
            *(float4*)&uout[(size_t)r * DIM + c0 + 4] =
                make_float4(o[4], o[5], o[6], o[7]);
            #pragma unroll
            for (int j = 0; j < 8; j++) {
                csum[j] += o[j];
                csum2[j] += o[j] * o[j];
            }
        }
    }
    float* ps  = sZ;           // 8 x 128
    float* ps2 = sZ + 1024;    // 8 x 128
    #pragma unroll
    for (int j = 0; j < 8; j++) {
        ps [ty * DIM + c0 + j] = csum[j];
        ps2[ty * DIM + c0 + j] = csum2[j];
    }
    __syncthreads();
    {
        int col = tid;   // 128 threads, one column each, both kinds
        float t1 = 0.0f, t2 = 0.0f;
        #pragma unroll
        for (int t = 0; t < 8; t++) {
            t1 += ps [t * DIM + col];
            t2 += ps2[t * DIM + col];
        }
        atomicAdd(&stats[col], t1);
        atomicAdd(&stats[DIM + col], t2);
    }
}

// ---------------- final: BN(u3) + layer-conv + pool -------------------------
__global__ void final_kernel(const float* __restrict__ gamma,
                             const float* __restrict__ beta,
                             const float* __restrict__ lwp,
                             const int* __restrict__ batch,
                             float* __restrict__ out, int rd) {
    __shared__ float sSc[DIM], sSh[DIM];
    const int tid = threadIdx.x;
    if (tid < DIM) {
        float mean = g_stats[0][tid] * (1.0f / N_NODES);
        float var  = g_stats[0][DIM + tid] * (1.0f / N_NODES) - mean * mean;
        float sc = rsqrtf(var + BN_EPS) * gamma[tid];
        sSc[tid] = sc;
        sSh[tid] = beta[tid] - mean * sc;
    }
    __syncthreads();
    int gw = (blockIdx.x * blockDim.x + tid) >> 5;
    if (gw >= N_NODES) return;
    int lane = tid & 31, c4 = lane << 2;
    float lw3 = __ldg(&lwp[N_LAYERS - 1]);
    float4 u = *(const float4*)&g_u[rd][(size_t)gw * DIM + c4];
    float4 a = *(const float4*)&g_acc[(size_t)gw * DIM + c4];
    float4 h;
    h.x = fmaf(u.x, sSc[c4],     sSh[c4]);
    h.y = fmaf(u.y, sSc[c4 + 1], sSh[c4 + 1]);
    h.z = fmaf(u.z, sSc[c4 + 2], sSh[c4 + 2]);
    h.w = fmaf(u.w, sSc[c4 + 3], sSh[c4 + 3]);
    a.x = fmaf(lw3, h.x, a.x); a.y = fmaf(lw3, h.y, a.y);
    a.z = fmaf(lw3, h.z, a.z); a.w = fmaf(lw3, h.w, a.w);
    int b = __ldg(&batch[gw]);
    float* p = &out[b * DIM + c4];
    asm volatile("red.global.add.v4.f32 [%0], {%1,%2,%3,%4};"
                 :: "l"(p), "f"(a.x), "f"(a.y), "f"(a.z), "f"(a.w) : "memory");
}

// ---------------- launch ----------------------------------------------------
extern "C" void kernel_launch(void* const* d_in, const int* in_sizes, int n_in,
                              void* d_out, int out_size) {
    const float* x     = (const float*)d_in[0];
    const int*   ei    = (const int*)  d_in[1];
    const int*   batch = (const int*)  d_in[2];
    const float* iw1   = (const float*)d_in[3];
    const float* ib1   = (const float*)d_in[4];
    const float* iw2   = (const float*)d_in[5];
    const float* ib2   = (const float*)d_in[6];
    const float* gw1   = (const float*)d_in[7];
    const float* gb1   = (const float*)d_in[8];
    const float* gw2   = (const float*)d_in[9];
    const float* gb2   = (const float*)d_in[10];
    const float* gamma = (const float*)d_in[11];
    const float* beta  = (const float*)d_in[12];
    const float* lw    = (const float*)d_in[13];
    const float* lb    = (const float*)d_in[14];
    float* out = (float*)d_out;

    cudaFuncSetAttribute(ini_gemm_kernel,
                         cudaFuncAttributeMaxDynamicSharedMemorySize, SMEM_INI);
    cudaFuncSetAttribute(gin_gemm_kernel,
                         cudaFuncAttributeMaxDynamicSharedMemorySize, SMEM_GIN);

    const int gemm_blocks = (N_NODES + 63) / 64;        // 782
    const int warp_blocks = (N_NODES * 32 + 255) / 256; // 6250

    init_kernel<<<(N_GRAPHS * DIM + 255) / 256, 256>>>(out);     // 1
    count_kernel<<<(N_EDGES + 255) / 256, 256>>>(ei);            // 2
    scan_kernel<<<1, 1024>>>();                                  // 3
    ini_gemm_kernel<<<gemm_blocks, NT, SMEM_INI>>>(              // 4
        x, iw1, ib1, iw2, ib2);
    fill_kernel<<<(N_EDGES + 255) / 256, 256>>>(ei);             // 5

    for (int l = 0; l < N_LAYERS; l++) {
        const float* gm = gamma + (size_t)(l > 0 ? l - 1 : 0) * DIM;
        const float* bt = beta  + (size_t)(l > 0 ? l - 1 : 0) * DIM;
        gather_kernel<<<warp_blocks, 256>>>(gm, bt, lw, lb, l, l & 1);
        gin_gemm_kernel<<<gemm_blocks, NT, SMEM_GIN>>>(
            gw1 + (size_t)l * DIM * DIM, gb1 + (size_t)l * DIM,
            gw2 + (size_t)l * DIM * DIM, gb2 + (size_t)l * DIM,
            l & 1, (l + 1) & 1);
    }

    final_kernel<<<warp_blocks, 256>>>(gamma + (size_t)(N_LAYERS - 1) * DIM,
                                       beta + (size_t)(N_LAYERS - 1) * DIM,
                                       lw, batch, out, 0);
}

// round 13
// speedup vs baseline: 1.2244x; 1.2244x over previous
#include <cuda_runtime.h>
#include <cuda_bf16.h>
#include <cstdint>

#define N_NODES 50000
#define N_EDGES 600000
#define N_GRAPHS 512
#define DIM 128
#define N_FEAT 78
#define N_LAYERS 4
#define BN_EPS 1e-5f

typedef unsigned long long ull;

// ---------------- scratch (device globals; no allocation allowed) ----------
__device__ float g_u[2][(size_t)N_NODES * DIM];  // ping-pong node features
__device__ float g_z[(size_t)N_NODES * DIM];     // gathered GIN input
__device__ float g_acc[(size_t)N_NODES * DIM];   // layer-conv accumulator
__device__ float g_stats[2][2 * DIM];            // double-buffered BN sums
__device__ int   g_deg[N_NODES];
__device__ int   g_ptr[N_NODES + 1];
__device__ int   g_cur[N_NODES];
__device__ int   g_csr[N_EDGES];                 // src sorted by dst
// W^T bf16 hi/lo pair-packed images: [layer][stage][hi/lo][n*64 + kpair]
__device__ unsigned g_wimg[N_LAYERS][2][2][128 * 64];

// ---------------- f32x2 packed-FMA helpers (FFMA2, used by ini) ------------
__device__ __forceinline__ void fma2(ull& d, ull a, ull b) {
    asm("fma.rn.f32x2 %0, %1, %2, %0;" : "+l"(d) : "l"(a), "l"(b));
}
__device__ __forceinline__ ull bcast2(float x) {
    unsigned u = __float_as_uint(x);
    ull r; asm("mov.b64 %0, {%1, %1};" : "=l"(r) : "r"(u)); return r;
}
__device__ __forceinline__ ull pack2(float x, float y) {
    ull r; asm("mov.b64 %0, {%1, %2};" : "=l"(r)
               : "r"(__float_as_uint(x)), "r"(__float_as_uint(y))); return r;
}
__device__ __forceinline__ float2 unpack2(ull v) {
    unsigned lo, hi;
    asm("mov.b64 {%0, %1}, %2;" : "=r"(lo), "=r"(hi) : "l"(v));
    return make_float2(__uint_as_float(lo), __uint_as_float(hi));
}

// ---------------- bf16 hi/lo split ------------------------------------------
__device__ __forceinline__ void split2(float x0, float x1,
                                       unsigned& hp, unsigned& lp) {
    __nv_bfloat16 h0 = __float2bfloat16(x0);
    __nv_bfloat16 h1 = __float2bfloat16(x1);
    __nv_bfloat162 H; H.x = h0; H.y = h1;
    __nv_bfloat162 L = __floats2bfloat162_rn(x0 - __bfloat162float(h0),
                                             x1 - __bfloat162float(h1));
    hp = *(unsigned*)&H;
    lp = *(unsigned*)&L;
}

// ---------------- warp-level bf16 MMA (baseline PTX, no arch-a) ------------
__device__ __forceinline__ void mma16816(float d[4],
                                         unsigned a0, unsigned a1,
                                         unsigned a2, unsigned a3,
                                         unsigned b0, unsigned b1) {
    asm volatile(
        "mma.sync.aligned.m16n8k16.row.col.f32.bf16.bf16.f32 "
        "{%0,%1,%2,%3}, {%4,%5,%6,%7}, {%8,%9}, {%0,%1,%2,%3};"
        : "+f"(d[0]), "+f"(d[1]), "+f"(d[2]), "+f"(d[3])
        : "r"(a0), "r"(a1), "r"(a2), "r"(a3), "r"(b0), "r"(b1));
}

// ---------------- legacy FFMA2 micro-kernel (ini only) ---------------------
template <int KSTEPS, int APAD>
__device__ __forceinline__ void mma8(const float* __restrict__ sA,
                                     const float* __restrict__ sW,
                                     ull acc[8][4], int ty, int c0) {
    #pragma unroll 2
    for (int kk = 0; kk < KSTEPS; kk += 4) {
        float a[8][4];
        #pragma unroll
        for (int i = 0; i < 8; i++)
            *(float4*)a[i] = *(const float4*)&sA[(ty * 8 + i) * APAD + kk];
        #pragma unroll
        for (int k = 0; k < 4; k++) {
            const ulonglong2* wp = (const ulonglong2*)&sW[(kk + k) * DIM + c0];
            ulonglong2 w01 = wp[0], w23 = wp[1];
            #pragma unroll
            for (int i = 0; i < 8; i++) {
                ull av = bcast2(a[i][k]);
                fma2(acc[i][0], av, w01.x); fma2(acc[i][1], av, w01.y);
                fma2(acc[i][2], av, w23.x); fma2(acc[i][3], av, w23.y);
            }
        }
    }
}

#define ZPAD 132
#define XPAD 80
#define NT 128
#define INI_WH   (40 * DIM)
#define INI_X    (64 * XPAD)
#define SMEM_INI ((INI_WH + INI_X + 64 * ZPAD) * (int)sizeof(float))

// gin mma kernel smem (unsigned words unless noted); pair-stride 68
#define WPAD 68
#define SZ_H 0                        // 128*68 u32 = 34816 B
#define SZ_L 34816
#define SW_H 69632                    // W images (stage-local)
#define SW_L 104448
#define SU_OFF 69632                  // f32 U tile reuses W region post-MMA
#define SBIAS 139264                  // 256 f32
#define SMEM_MMA 140288

// ---------------- CSR build --------------------------------------------------
__global__ void init_kernel(float* __restrict__ out) {
    int i = blockIdx.x * blockDim.x + threadIdx.x;
    if (i < N_NODES) g_deg[i] = 0;
    if (i < N_GRAPHS * DIM) out[i] = 0.0f;
}

__global__ void count_kernel(const int* __restrict__ ei) {
    int e = blockIdx.x * blockDim.x + threadIdx.x;
    if (e < N_EDGES) atomicAdd(&g_deg[__ldg(&ei[N_EDGES + e])], 1);
}

__global__ void scan_kernel() {
    __shared__ int ssum[1024];
    const int t = threadIdx.x;
    const int CH = (N_NODES + 1023) / 1024;
    const int base = t * CH;
    int sum = 0;
    for (int i = 0; i < CH; i++) {
        int idx = base + i;
        if (idx < N_NODES) sum += g_deg[idx];
    }
    ssum[t] = sum;
    __syncthreads();
    for (int off = 1; off < 1024; off <<= 1) {
        int v = (t >= off) ? ssum[t - off] : 0;
        __syncthreads();
        ssum[t] += v;
        __syncthreads();
    }
    int run = ssum[t] - sum;
    for (int i = 0; i < CH; i++) {
        int idx = base + i;
        if (idx < N_NODES) {
            g_ptr[idx] = run;
            g_cur[idx] = run;
            run += g_deg[idx];
        }
    }
    if (t == 0) g_ptr[N_NODES] = N_EDGES;
}

__global__ void fill_kernel(const int* __restrict__ ei) {
    int e = blockIdx.x * blockDim.x + threadIdx.x;
    if (e >= N_EDGES) return;
    int dst = __ldg(&ei[N_EDGES + e]);
    int pos = atomicAdd(&g_cur[dst], 1);
    g_csr[pos] = __ldg(&ei[e]);
}

// ---------------- W images: W^T bf16 hi/lo, k-pair packed -------------------
// g_wimg[l][s][h][n*64 + kp] = bf16x2 { W[2kp][n], W[2kp+1][n] }
__global__ void wsplit_kernel(const float* __restrict__ gw1,
                              const float* __restrict__ gw2) {
    int t = blockIdx.x * blockDim.x + threadIdx.x;
    if (t >= N_LAYERS * 2 * 128 * 64) return;
    int kp = t & 63;
    int n  = (t >> 6) & 127;
    int s  = (t >> 13) & 1;
    int l  = t >> 14;
    const float* W = (s ? gw2 : gw1) + (size_t)l * DIM * DIM;
    int k = kp << 1;
    unsigned hp, lp;
    split2(W[k * DIM + n], W[(k + 1) * DIM + n], hp, lp);
    g_wimg[l][s][0][n * 64 + kp] = hp;
    g_wimg[l][s][1][n * 64 + kp] = lp;
}

// ---------------- ini embed: u0 = relu(x@W1+b1)@W2+b2 (FFMA2) --------------
__global__ void __launch_bounds__(NT, 3)
ini_gemm_kernel(const float* __restrict__ x,
                const float* __restrict__ w1, const float* __restrict__ b1,
                const float* __restrict__ w2, const float* __restrict__ b2) {
    extern __shared__ float sm[];
    float* sW = sm;
    float* sX = sm + INI_WH;
    float* sT = sX + INI_X;
    const int tid = threadIdx.x;
    const int rbase = blockIdx.x * 64;

    for (int i = tid; i < 64 * XPAD; i += NT) {
        int r = i / XPAD, c = i - r * XPAD;
        sX[i] = (c < N_FEAT && rbase + r < N_NODES)
                ? x[(size_t)(rbase + r) * N_FEAT + c] : 0.0f;
    }

    const int ty = tid >> 4, tx = tid & 15, c0 = tx << 3;
    ull acc[8][4];

    {
        ull b[4];
        #pragma unroll
        for (int j = 0; j < 4; j++)
            b[j] = pack2(b1[c0 + 2 * j], b1[c0 + 2 * j + 1]);
        #pragma unroll
        for (int i = 0; i < 8; i++)
            #pragma unroll
            for (int j = 0; j < 4; j++) acc[i][j] = b[j];
    }
    #pragma unroll 1
    for (int h = 0; h < 2; h++) {
        __syncthreads();
        for (int i = tid * 4; i < 40 * DIM; i += NT * 4) {
            int gk = h * 40 * DIM + i;
            float4 v = make_float4(0, 0, 0, 0);
            if (gk < N_FEAT * DIM) v = *(const float4*)&w1[gk];
            *(float4*)&sW[i] = v;
        }
        __syncthreads();
        mma8<40, XPAD>(sX + h * 40, sW, acc, ty, c0);
    }
    __syncthreads();

    #pragma unroll
    for (int i = 0; i < 8; i++)
        #pragma unroll
        for (int j = 0; j < 4; j++) {
            float2 f = unpack2(acc[i][j]);
            sT[(ty * 8 + i) * ZPAD + c0 + 2 * j]     = fmaxf(f.x, 0.0f);
            sT[(ty * 8 + i) * ZPAD + c0 + 2 * j + 1] = fmaxf(f.y, 0.0f);
        }

    {
        ull b[4];
        #pragma unroll
        for (int j = 0; j < 4; j++)
            b[j] = pack2(b2[c0 + 2 * j], b2[c0 + 2 * j + 1]);
        #pragma unroll
        for (int i = 0; i < 8; i++)
            #pragma unroll
            for (int j = 0; j < 4; j++) acc[i][j] = b[j];
    }
    #pragma unroll 1
    for (int q = 0; q < 4; q++) {
        __syncthreads();
        for (int i = tid * 4; i < 32 * DIM; i += NT * 4)
            *(float4*)&sW[i] = *(const float4*)&w2[q * 32 * DIM + i];
        __syncthreads();
        mma8<32, ZPAD>(sT + q * 32, sW, acc, ty, c0);
    }

    #pragma unroll
    for (int i = 0; i < 8; i++) {
        int r = rbase + ty * 8 + i;
        if (r < N_NODES) {
            float2 f0 = unpack2(acc[i][0]), f1 = unpack2(acc[i][1]);
            float2 f2 = unpack2(acc[i][2]), f3 = unpack2(acc[i][3]);
            *(float4*)&g_u[0][(size_t)r * DIM + c0] =
                make_float4(f0.x, f0.y, f1.x, f1.y);
            *(float4*)&g_u[0][(size_t)r * DIM + c0 + 4] =
                make_float4(f2.x, f2.y, f3.x, f3.y);
        }
    }
}

// ---------------- gather: z = sc*(u+sum u_src)+(deg+1)*sh; acc += lw*h -----
__global__ void __launch_bounds__(256)
gather_kernel(const float* __restrict__ gamma, const float* __restrict__ beta,
              const float* __restrict__ lwp, const float* __restrict__ lbp,
              int layer, int rd) {
    if (blockIdx.x == 0 && threadIdx.x < 2 * DIM)
        g_stats[(layer + 1) & 1][threadIdx.x] = 0.0f;
    int node = (blockIdx.x * blockDim.x + threadIdx.x) >> 5;
    if (node >= N_NODES) return;
    const float* __restrict__ uin = g_u[rd];
    const int lane = threadIdx.x & 31, cc = lane << 2;

    float4 scv = make_float4(1, 1, 1, 1), shv = make_float4(0, 0, 0, 0);
    if (layer > 0) {
        const float* st = g_stats[layer & 1];
        float sc[4], sh[4];
        #pragma unroll
        for (int j = 0; j < 4; j++) {
            float mean = __ldg(&st[cc + j]) * (1.0f / N_NODES);
            float var  = __ldg(&st[DIM + cc + j]) * (1.0f / N_NODES)
                         - mean * mean;
            sc[j] = rsqrtf(var + BN_EPS) * __ldg(&gamma[cc + j]);
            sh[j] = __ldg(&beta[cc + j]) - mean * sc[j];
        }
        scv = make_float4(sc[0], sc[1], sc[2], sc[3]);
        shv = make_float4(sh[0], sh[1], sh[2], sh[3]);
    }

    float4 un = *(const float4*)&uin[(size_t)node * DIM + cc];
    int p0 = __ldg(&g_ptr[node]), p1 = __ldg(&g_ptr[node + 1]);
    float4 s0 = un, s1 = make_float4(0, 0, 0, 0);
    float4 s2 = make_float4(0, 0, 0, 0), s3 = make_float4(0, 0, 0, 0);
    int k = p0;
    for (; k + 4 <= p1; k += 4) {
        int sa = __ldg(&g_csr[k]),      sb = __ldg(&g_csr[k + 1]);
        int sc2 = __ldg(&g_csr[k + 2]), sd = __ldg(&g_csr[k + 3]);
        float4 ua = *(const float4*)&uin[(size_t)sa * DIM + cc];
        float4 ub = *(const float4*)&uin[(size_t)sb * DIM + cc];
        float4 uc = *(const float4*)&uin[(size_t)sc2 * DIM + cc];
        float4 ud = *(const float4*)&uin[(size_t)sd * DIM + cc];
        s0.x += ua.x; s0.y += ua.y; s0.z += ua.z; s0.w += ua.w;
        s1.x += ub.x; s1.y += ub.y; s1.z += ub.z; s1.w += ub.w;
        s2.x += uc.x; s2.y += uc.y; s2.z += uc.z; s2.w += uc.w;
        s3.x += ud.x; s3.y += ud.y; s3.z += ud.z; s3.w += ud.w;
    }
    for (; k < p1; k++) {
        int sa = __ldg(&g_csr[k]);
        float4 ua = *(const float4*)&uin[(size_t)sa * DIM + cc];
        s0.x += ua.x; s0.y += ua.y; s0.z += ua.z; s0.w += ua.w;
    }
    s0.x += s1.x + s2.x + s3.x; s0.y += s1.y + s2.y + s3.y;
    s0.z += s1.z + s2.z + s3.z; s0.w += s1.w + s2.w + s3.w;
    float dp1 = (float)(p1 - p0 + 1);
    float4 z4;
    z4.x = fmaf(scv.x, s0.x, dp1 * shv.x);
    z4.y = fmaf(scv.y, s0.y, dp1 * shv.y);
    z4.z = fmaf(scv.z, s0.z, dp1 * shv.z);
    z4.w = fmaf(scv.w, s0.w, dp1 * shv.w);
    *(float4*)&g_z[(size_t)node * DIM + cc] = z4;

    if (layer > 0) {
        const float lw_prev = __ldg(&lwp[layer - 1]);
        float4 h;
        h.x = fmaf(un.x, scv.x, shv.x); h.y = fmaf(un.y, scv.y, shv.y);
        h.z = fmaf(un.z, scv.z, shv.z); h.w = fmaf(un.w, scv.w, shv.w);
        float4 a;
        if (layer == 1) {
            float lb = __ldg(lbp);
            a = make_float4(lb, lb, lb, lb);
        } else {
            a = *(const float4*)&g_acc[(size_t)node * DIM + cc];
        }
        a.x = fmaf(lw_prev, h.x, a.x); a.y = fmaf(lw_prev, h.y, a.y);
        a.z = fmaf(lw_prev, h.z, a.z); a.w = fmaf(lw_prev, h.w, a.w);
        *(float4*)&g_acc[(size_t)node * DIM + cc] = a;
    }
}

// ---------------- GIN MLP via mma.sync bf16x3 -------------------------------
// 256 threads = 8 warps; warp w owns rows w*16..w*16+15 of a 128-row tile.
__device__ __forceinline__ void mma_stage(const unsigned* __restrict__ sZh,
                                          const unsigned* __restrict__ sZl,
                                          const unsigned* __restrict__ sWh,
                                          const unsigned* __restrict__ sWl,
                                          const float* __restrict__ bias,
                                          float d[16][4], int m0, int lane) {
    const int g = lane >> 2, q = lane & 3;
    #pragma unroll
    for (int nt = 0; nt < 16; nt++) {
        float bx = bias[nt * 8 + q * 2];
        float by = bias[nt * 8 + q * 2 + 1];
        d[nt][0] = bx; d[nt][1] = by; d[nt][2] = bx; d[nt][3] = by;
    }
    const unsigned* A0h = sZh + (m0 + g) * WPAD;
    const unsigned* A1h = sZh + (m0 + g + 8) * WPAD;
    const unsigned* A0l = sZl + (m0 + g) * WPAD;
    const unsigned* A1l = sZl + (m0 + g + 8) * WPAD;
    #pragma unroll 1
    for (int k0 = 0; k0 < 8; k0++) {
        int kp = k0 * 8 + q;
        unsigned ah0 = A0h[kp], ah1 = A1h[kp];
        unsigned ah2 = A0h[kp + 4], ah3 = A1h[kp + 4];
        unsigned al0 = A0l[kp], al1 = A1l[kp];
        unsigned al2 = A0l[kp + 4], al3 = A1l[kp + 4];
        #pragma unroll
        for (int nt = 0; nt < 16; nt++) {
            int bo = (nt * 8 + g) * WPAD + kp;
            unsigned bh0 = sWh[bo], bh1 = sWh[bo + 4];
            unsigned bl0 = sWl[bo], bl1 = sWl[bo + 4];
            mma16816(d[nt], ah0, ah1, ah2, ah3, bh0, bh1);
            mma16816(d[nt], ah0, ah1, ah2, ah3, bl0, bl1);
            mma16816(d[nt], al0, al1, al2, al3, bh0, bh1);
        }
    }
}

__global__ void __launch_bounds__(256, 1)
gin_mma_kernel(const float* __restrict__ b1, const float* __restrict__ b2,
               int layer, int rd, int sout) {
    extern __shared__ char smem[];
    unsigned* sZh = (unsigned*)(smem + SZ_H);
    unsigned* sZl = (unsigned*)(smem + SZ_L);
    unsigned* sWh = (unsigned*)(smem + SW_H);
    unsigned* sWl = (unsigned*)(smem + SW_L);
    float* sU = (float*)(smem + SU_OFF);
    float* sBias = (float*)(smem + SBIAS);
    const int tid = threadIdx.x;
    const int wid = tid >> 5, lane = tid & 31;
    const int rbase = blockIdx.x * 128;
    const int valid = min(128, N_NODES - rbase);
    const int m0 = wid * 16;
    const int g = lane >> 2, q = lane & 3;

    if (tid < 128) { sBias[tid] = b1[tid]; sBias[128 + tid] = b2[tid]; }

    // Z tile -> bf16 hi/lo pairs (row-major, stride WPAD u32)
    {
        const float* zb = g_z + (size_t)rbase * DIM;
        for (int i = tid; i < 128 * 32; i += 256) {
            int r = i >> 5, c4 = (i & 31) << 2;
            float4 z = make_float4(0, 0, 0, 0);
            if (r < valid) z = *(const float4*)&zb[r * DIM + c4];
            unsigned hp0, lp0, hp1, lp1;
            split2(z.x, z.y, hp0, lp0);
            split2(z.z, z.w, hp1, lp1);
            int o = r * WPAD + (c4 >> 1);
            sZh[o] = hp0; sZh[o + 1] = hp1;
            sZl[o] = lp0; sZl[o + 1] = lp1;
        }
    }
    // W1 images
    for (int i = tid; i < 128 * 16; i += 256) {
        int row = i >> 4, qq = i & 15;
        *(uint4*)&sWh[row * WPAD + qq * 4] =
            ((const uint4*)&g_wimg[layer][0][0][row * 64])[qq];
        *(uint4*)&sWl[row * WPAD + qq * 4] =
            ((const uint4*)&g_wimg[layer][0][1][row * 64])[qq];
    }
    __syncthreads();

    float d[16][4];

    // ---- stage 1: D = Z @ W1 + b1 ----
    mma_stage(sZh, sZl, sWh, sWl, sBias, d, m0, lane);

    // epilogue 1: T = relu(D) -> rebuild A pairs in place (own rows only)
    {
        int r0 = (m0 + g) * WPAD, r1 = (m0 + g + 8) * WPAD;
        #pragma unroll
        for (int nt = 0; nt < 16; nt++) {
            int kp = nt * 4 + q;
            unsigned hp, lp;
            split2(fmaxf(d[nt][0], 0.0f), fmaxf(d[nt][1], 0.0f), hp, lp);
            sZh[r0 + kp] = hp; sZl[r0 + kp] = lp;
            split2(fmaxf(d[nt][2], 0.0f), fmaxf(d[nt][3], 0.0f), hp, lp);
            sZh[r1 + kp] = hp; sZl[r1 + kp] = lp;
        }
    }
    __syncthreads();
    // W2 images
    for (int i = tid; i < 128 * 16; i += 256) {
        int row = i >> 4, qq = i & 15;
        *(uint4*)&sWh[row * WPAD + qq * 4] =
            ((const uint4*)&g_wimg[layer][1][0][row * 64])[qq];
        *(uint4*)&sWl[row * WPAD + qq * 4] =
            ((const uint4*)&g_wimg[layer][1][1][row * 64])[qq];
    }
    __syncthreads();

    // ---- stage 2: D = T @ W2 + b2 ----
    mma_stage(sZh, sZl, sWh, sWl, sBias + 128, d, m0, lane);
    __syncthreads();   // all W reads done; reuse region as sU

    // epilogue 2: u = relu(D) -> sU
    {
        int r0 = m0 + g, r1 = m0 + g + 8;
        #pragma unroll
        for (int nt = 0; nt < 16; nt++) {
            int c = nt * 8 + q * 2;
            *(float2*)&sU[r0 * 132 + c] =
                make_float2(fmaxf(d[nt][0], 0.0f), fmaxf(d[nt][1], 0.0f));
            *(float2*)&sU[r1 * 132 + c] =
                make_float2(fmaxf(d[nt][2], 0.0f), fmaxf(d[nt][3], 0.0f));
        }
    }
    __syncthreads();

    // stats + coalesced u store
    if (tid < 128) {
        float s = 0.0f, s2 = 0.0f;
        for (int r = 0; r < valid; r++) {
            float v = sU[r * 132 + tid];
            s += v; s2 += v * v;
        }
        atomicAdd(&g_stats[sout][tid], s);
        atomicAdd(&g_stats[sout][DIM + tid], s2);
    }
    {
        float* __restrict__ uout = g_u[rd ^ 1];
        for (int i = tid; i < 128 * 32; i += 256) {
            int r = i >> 5, c4 = (i & 31) << 2;
            if (r < valid)
                *(float4*)&uout[(size_t)(rbase + r) * DIM + c4] =
                    *(const float4*)&sU[r * 132 + c4];
        }
    }
}

// ---------------- final: BN(u3) + layer-conv + pool -------------------------
__global__ void final_kernel(const float* __restrict__ gamma,
                             const float* __restrict__ beta,
                             const float* __restrict__ lwp,
                             const int* __restrict__ batch,
                             float* __restrict__ out, int rd) {
    __shared__ float sSc[DIM], sSh[DIM];
    const int tid = threadIdx.x;
    if (tid < DIM) {
        float mean = g_stats[0][tid] * (1.0f / N_NODES);
        float var  = g_stats[0][DIM + tid] * (1.0f / N_NODES) - mean * mean;
        float sc = rsqrtf(var + BN_EPS) * gamma[tid];
        sSc[tid] = sc;
        sSh[tid] = beta[tid] - mean * sc;
    }
    __syncthreads();
    int gw = (blockIdx.x * blockDim.x + tid) >> 5;
    if (gw >= N_NODES) return;
    int lane = tid & 31, c4 = lane << 2;
    float lw3 = __ldg(&lwp[N_LAYERS - 1]);
    float4 u = *(const float4*)&g_u[rd][(size_t)gw * DIM + c4];
    float4 a = *(const float4*)&g_acc[(size_t)gw * DIM + c4];
    float4 h;
    h.x = fmaf(u.x, sSc[c4],     sSh[c4]);
    h.y = fmaf(u.y, sSc[c4 + 1], sSh[c4 + 1]);
    h.z = fmaf(u.z, sSc[c4 + 2], sSh[c4 + 2]);
    h.w = fmaf(u.w, sSc[c4 + 3], sSh[c4 + 3]);
    a.x = fmaf(lw3, h.x, a.x); a.y = fmaf(lw3, h.y, a.y);
    a.z = fmaf(lw3, h.z, a.z); a.w = fmaf(lw3, h.w, a.w);
    int b = __ldg(&batch[gw]);
    float* p = &out[b * DIM + c4];
    asm volatile("red.global.add.v4.f32 [%0], {%1,%2,%3,%4};"
                 :: "l"(p), "f"(a.x), "f"(a.y), "f"(a.z), "f"(a.w) : "memory");
}

// ---------------- launch ----------------------------------------------------
extern "C" void kernel_launch(void* const* d_in, const int* in_sizes, int n_in,
                              void* d_out, int out_size) {
    const float* x     = (const float*)d_in[0];
    const int*   ei    = (const int*)  d_in[1];
    const int*   batch = (const int*)  d_in[2];
    const float* iw1   = (const float*)d_in[3];
    const float* ib1   = (const float*)d_in[4];
    const float* iw2   = (const float*)d_in[5];
    const float* ib2   = (const float*)d_in[6];
    const float* gw1   = (const float*)d_in[7];
    const float* gb1   = (const float*)d_in[8];
    const float* gw2   = (const float*)d_in[9];
    const float* gb2   = (const float*)d_in[10];
    const float* gamma = (const float*)d_in[11];
    const float* beta  = (const float*)d_in[12];
    const float* lw    = (const float*)d_in[13];
    const float* lb    = (const float*)d_in[14];
    float* out = (float*)d_out;

    cudaFuncSetAttribute(ini_gemm_kernel,
                         cudaFuncAttributeMaxDynamicSharedMemorySize, SMEM_INI);
    cudaFuncSetAttribute(gin_mma_kernel,
                         cudaFuncAttributeMaxDynamicSharedMemorySize, SMEM_MMA);

    const int ini_blocks  = (N_NODES + 63) / 64;         // 782
    const int gin_blocks  = (N_NODES + 127) / 128;       // 391
    const int warp_blocks = (N_NODES * 32 + 255) / 256;  // 6250

    init_kernel<<<(N_GRAPHS * DIM + 255) / 256, 256>>>(out);     // 1
    count_kernel<<<(N_EDGES + 255) / 256, 256>>>(ei);            // 2
    scan_kernel<<<1, 1024>>>();                                  // 3
    ini_gemm_kernel<<<ini_blocks, NT, SMEM_INI>>>(               // 4
        x, iw1, ib1, iw2, ib2);
    fill_kernel<<<(N_EDGES + 255) / 256, 256>>>(ei);             // 5
    wsplit_kernel<<<(N_LAYERS * 2 * 128 * 64 + 255) / 256, 256>>>(gw1, gw2);

    for (int l = 0; l < N_LAYERS; l++) {
        const float* gm = gamma + (size_t)(l > 0 ? l - 1 : 0) * DIM;
        const float* bt = beta  + (size_t)(l > 0 ? l - 1 : 0) * DIM;
        gather_kernel<<<warp_blocks, 256>>>(gm, bt, lw, lb, l, l & 1);
        gin_mma_kernel<<<gin_blocks, 256, SMEM_MMA>>>(
            gb1 + (size_t)l * DIM, gb2 + (size_t)l * DIM,
            l, l & 1, (l + 1) & 1);
    }

    final_kernel<<<warp_blocks, 256>>>(gamma + (size_t)(N_LAYERS - 1) * DIM,
                                       beta + (size_t)(N_LAYERS - 1) * DIM,
                                       lw, batch, out, 0);
}

// round 14
// speedup vs baseline: 1.2486x; 1.0198x over previous
#include <cuda_runtime.h>
#include <cuda_bf16.h>
#include <cstdint>

#define N_NODES 50000
#define N_EDGES 600000
#define N_GRAPHS 512
#define DIM 128
#define N_FEAT 78
#define N_LAYERS 4
#define BN_EPS 1e-5f
#define NL1 (N_LAYERS + 1)

// ---------------- scratch (device globals; no allocation allowed) ----------
__device__ float g_u[2][(size_t)N_NODES * DIM];  // ping-pong node features
__device__ float g_z[(size_t)N_NODES * DIM];     // gathered GIN input
__device__ float g_acc[(size_t)N_NODES * DIM];   // layer-conv accumulator
__device__ float g_stats[2][2 * DIM];            // double-buffered BN sums
__device__ int   g_deg[N_NODES];
__device__ int   g_ptr[N_NODES + 1];
__device__ int   g_cur[N_NODES];
__device__ int   g_csr[N_EDGES];                 // src sorted by dst
// W^T bf16 hi/lo pair-packed images; slot N_LAYERS = ini weights
__device__ unsigned g_wimg[NL1][2][2][128 * 64];

// ---------------- bf16 hi/lo split ------------------------------------------
__device__ __forceinline__ void split2(float x0, float x1,
                                       unsigned& hp, unsigned& lp) {
    __nv_bfloat16 h0 = __float2bfloat16(x0);
    __nv_bfloat16 h1 = __float2bfloat16(x1);
    __nv_bfloat162 H; H.x = h0; H.y = h1;
    __nv_bfloat162 L = __floats2bfloat162_rn(x0 - __bfloat162float(h0),
                                             x1 - __bfloat162float(h1));
    hp = *(unsigned*)&H;
    lp = *(unsigned*)&L;
}

// ---------------- warp-level bf16 MMA (baseline PTX, no arch-a) ------------
__device__ __forceinline__ void mma16816(float d[4],
                                         unsigned a0, unsigned a1,
                                         unsigned a2, unsigned a3,
                                         unsigned b0, unsigned b1) {
    asm volatile(
        "mma.sync.aligned.m16n8k16.row.col.f32.bf16.bf16.f32 "
        "{%0,%1,%2,%3}, {%4,%5,%6,%7}, {%8,%9}, {%0,%1,%2,%3};"
        : "+f"(d[0]), "+f"(d[1]), "+f"(d[2]), "+f"(d[3])
        : "r"(a0), "r"(a1), "r"(a2), "r"(a3), "r"(b0), "r"(b1));
}

// smem map (bytes); pair-stride 68 u32 (conflict-free: bank = 4g+q)
#define WPAD 68
#define SZ_H 0                        // 128*68 u32 = 34816 B
#define SZ_L 34816
#define SW_H 69632                    // W images (stage-local)
#define SW_L 104448
#define SU_OFF 69632                  // f32 U tile reuses W region post-MMA
#define SBIAS 139264                  // 256 f32
#define SMEM_MMA 140288

// ---------------- 2x4-warp mma stage: warp (mw,nw) -> m64 x n32 ------------
// A rows m0+mt*16, B rows (cols of D) n0+nt*8. 3-product bf16 split.
template <int KSTEPS>
__device__ __forceinline__ void mma_stage(const unsigned* __restrict__ sAh,
                                          const unsigned* __restrict__ sAl,
                                          const unsigned* __restrict__ sWh,
                                          const unsigned* __restrict__ sWl,
                                          const float* __restrict__ bias,
                                          float d[4][4][4],
                                          int m0, int n0, int lane) {
    const int g = lane >> 2, q = lane & 3;
    #pragma unroll
    for (int mt = 0; mt < 4; mt++)
        #pragma unroll
        for (int nt = 0; nt < 4; nt++) {
            float bx = bias[n0 + nt * 8 + q * 2];
            float by = bias[n0 + nt * 8 + q * 2 + 1];
            d[mt][nt][0] = bx; d[mt][nt][1] = by;
            d[mt][nt][2] = bx; d[mt][nt][3] = by;
        }
    #pragma unroll 1
    for (int k0 = 0; k0 < KSTEPS; k0++) {
        const int kp = k0 * 8 + q;
        unsigned ah[4][4], al[4][4];
        #pragma unroll
        for (int mt = 0; mt < 4; mt++) {
            int r0 = (m0 + mt * 16 + g) * WPAD, r1 = r0 + 8 * WPAD;
            ah[mt][0] = sAh[r0 + kp];     ah[mt][1] = sAh[r1 + kp];
            ah[mt][2] = sAh[r0 + kp + 4]; ah[mt][3] = sAh[r1 + kp + 4];
            al[mt][0] = sAl[r0 + kp];     al[mt][1] = sAl[r1 + kp];
            al[mt][2] = sAl[r0 + kp + 4]; al[mt][3] = sAl[r1 + kp + 4];
        }
        unsigned bh[4][2], bl[4][2];
        #pragma unroll
        for (int nt = 0; nt < 4; nt++) {
            int bo = (n0 + nt * 8 + g) * WPAD + kp;
            bh[nt][0] = sWh[bo]; bh[nt][1] = sWh[bo + 4];
            bl[nt][0] = sWl[bo]; bl[nt][1] = sWl[bo + 4];
        }
        #pragma unroll
        for (int mt = 0; mt < 4; mt++)
            #pragma unroll
            for (int nt = 0; nt < 4; nt++) {
                mma16816(d[mt][nt], ah[mt][0], ah[mt][1], ah[mt][2], ah[mt][3],
                         bh[nt][0], bh[nt][1]);
                mma16816(d[mt][nt], ah[mt][0], ah[mt][1], ah[mt][2], ah[mt][3],
                         bl[nt][0], bl[nt][1]);
                mma16816(d[mt][nt], al[mt][0], al[mt][1], al[mt][2], al[mt][3],
                         bh[nt][0], bh[nt][1]);
            }
    }
}

// relu(D) -> rebuild A pairs in sAh/sAl (for next stage)
__device__ __forceinline__ void epilogue_rebuild(unsigned* __restrict__ sAh,
                                                 unsigned* __restrict__ sAl,
                                                 float d[4][4][4],
                                                 int m0, int n0, int lane) {
    const int g = lane >> 2, q = lane & 3;
    #pragma unroll
    for (int mt = 0; mt < 4; mt++)
        #pragma unroll
        for (int nt = 0; nt < 4; nt++) {
            int kp = (n0 >> 1) + nt * 4 + q;
            int r0 = (m0 + mt * 16 + g) * WPAD, r1 = r0 + 8 * WPAD;
            unsigned hp, lp;
            split2(fmaxf(d[mt][nt][0], 0.0f), fmaxf(d[mt][nt][1], 0.0f), hp, lp);
            sAh[r0 + kp] = hp; sAl[r0 + kp] = lp;
            split2(fmaxf(d[mt][nt][2], 0.0f), fmaxf(d[mt][nt][3], 0.0f), hp, lp);
            sAh[r1 + kp] = hp; sAl[r1 + kp] = lp;
        }
}

// D (+relu opt) -> sU [128 x 132 f32]
__device__ __forceinline__ void epilogue_store(float* __restrict__ sU,
                                               float d[4][4][4],
                                               int m0, int n0, int lane,
                                               bool do_relu) {
    const int g = lane >> 2, q = lane & 3;
    #pragma unroll
    for (int mt = 0; mt < 4; mt++)
        #pragma unroll
        for (int nt = 0; nt < 4; nt++) {
            int c = n0 + nt * 8 + q * 2;
            int r0 = m0 + mt * 16 + g, r1 = r0 + 8;
            float v0 = d[mt][nt][0], v1 = d[mt][nt][1];
            float v2 = d[mt][nt][2], v3 = d[mt][nt][3];
            if (do_relu) {
                v0 = fmaxf(v0, 0.0f); v1 = fmaxf(v1, 0.0f);
                v2 = fmaxf(v2, 0.0f); v3 = fmaxf(v3, 0.0f);
            }
            *(float2*)&sU[r0 * 132 + c] = make_float2(v0, v1);
            *(float2*)&sU[r1 * 132 + c] = make_float2(v2, v3);
        }
}

// ---------------- CSR build --------------------------------------------------
__global__ void init_kernel(float* __restrict__ out) {
    int i = blockIdx.x * blockDim.x + threadIdx.x;
    if (i < N_NODES) g_deg[i] = 0;
    if (i < N_GRAPHS * DIM) out[i] = 0.0f;
}

__global__ void count_kernel(const int* __restrict__ ei) {
    int e = blockIdx.x * blockDim.x + threadIdx.x;
    if (e < N_EDGES) atomicAdd(&g_deg[__ldg(&ei[N_EDGES + e])], 1);
}

__global__ void scan_kernel() {
    __shared__ int ssum[1024];
    const int t = threadIdx.x;
    const int CH = (N_NODES + 1023) / 1024;
    const int base = t * CH;
    int sum = 0;
    for (int i = 0; i < CH; i++) {
        int idx = base + i;
        if (idx < N_NODES) sum += g_deg[idx];
    }
    ssum[t] = sum;
    __syncthreads();
    for (int off = 1; off < 1024; off <<= 1) {
        int v = (t >= off) ? ssum[t - off] : 0;
        __syncthreads();
        ssum[t] += v;
        __syncthreads();
    }
    int run = ssum[t] - sum;
    for (int i = 0; i < CH; i++) {
        int idx = base + i;
        if (idx < N_NODES) {
            g_ptr[idx] = run;
            g_cur[idx] = run;
            run += g_deg[idx];
        }
    }
    if (t == 0) g_ptr[N_NODES] = N_EDGES;
}

__global__ void fill_kernel(const int* __restrict__ ei) {
    int e = blockIdx.x * blockDim.x + threadIdx.x;
    if (e >= N_EDGES) return;
    int dst = __ldg(&ei[N_EDGES + e]);
    int pos = atomicAdd(&g_cur[dst], 1);
    g_csr[pos] = __ldg(&ei[e]);
}

// ---------------- W images: W^T bf16 hi/lo, k-pair packed -------------------
__global__ void wsplit_kernel(const float* __restrict__ gw1,
                              const float* __restrict__ gw2,
                              const float* __restrict__ iw1,
                              const float* __restrict__ iw2) {
    int t = blockIdx.x * blockDim.x + threadIdx.x;
    if (t >= NL1 * 2 * 128 * 64) return;
    int kp = t & 63;
    int n  = (t >> 6) & 127;
    int s  = (t >> 13) & 1;
    int l  = t >> 14;
    const float* W;
    int K;
    if (l < N_LAYERS) {
        W = (s ? gw2 : gw1) + (size_t)l * DIM * DIM;
        K = DIM;
    } else {
        W = s ? iw2 : iw1;
        K = s ? DIM : N_FEAT;
    }
    int k = kp << 1;
    float x0 = (k < K)     ? W[(size_t)k * DIM + n]       : 0.0f;
    float x1 = (k + 1 < K) ? W[(size_t)(k + 1) * DIM + n] : 0.0f;
    unsigned hp, lp;
    split2(x0, x1, hp, lp);
    g_wimg[l][s][0][n * 64 + kp] = hp;
    g_wimg[l][s][1][n * 64 + kp] = lp;
}

// ---------------- gather: z = sc*(u+sum u_src)+(deg+1)*sh; acc += lw*h -----
__global__ void __launch_bounds__(256)
gather_kernel(const float* __restrict__ gamma, const float* __restrict__ beta,
              const float* __restrict__ lwp, const float* __restrict__ lbp,
              int layer, int rd) {
    if (blockIdx.x == 0 && threadIdx.x < 2 * DIM)
        g_stats[(layer + 1) & 1][threadIdx.x] = 0.0f;
    int node = (blockIdx.x * blockDim.x + threadIdx.x) >> 5;
    if (node >= N_NODES) return;
    const float* __restrict__ uin = g_u[rd];
    const int lane = threadIdx.x & 31, cc = lane << 2;

    float4 scv = make_float4(1, 1, 1, 1), shv = make_float4(0, 0, 0, 0);
    if (layer > 0) {
        const float* st = g_stats[layer & 1];
        float sc[4], sh[4];
        #pragma unroll
        for (int j = 0; j < 4; j++) {
            float mean = __ldg(&st[cc + j]) * (1.0f / N_NODES);
            float var  = __ldg(&st[DIM + cc + j]) * (1.0f / N_NODES)
                         - mean * mean;
            sc[j] = rsqrtf(var + BN_EPS) * __ldg(&gamma[cc + j]);
            sh[j] = __ldg(&beta[cc + j]) - mean * sc[j];
        }
        scv = make_float4(sc[0], sc[1], sc[2], sc[3]);
        shv = make_float4(sh[0], sh[1], sh[2], sh[3]);
    }

    float4 un = *(const float4*)&uin[(size_t)node * DIM + cc];
    int p0 = __ldg(&g_ptr[node]), p1 = __ldg(&g_ptr[node + 1]);
    float4 s0 = un, s1 = make_float4(0, 0, 0, 0);
    float4 s2 = make_float4(0, 0, 0, 0), s3 = make_float4(0, 0, 0, 0);
    int k = p0;
    for (; k + 4 <= p1; k += 4) {
        int sa = __ldg(&g_csr[k]),      sb = __ldg(&g_csr[k + 1]);
        int sc2 = __ldg(&g_csr[k + 2]), sd = __ldg(&g_csr[k + 3]);
        float4 ua = *(const float4*)&uin[(size_t)sa * DIM + cc];
        float4 ub = *(const float4*)&uin[(size_t)sb * DIM + cc];
        float4 uc = *(const float4*)&uin[(size_t)sc2 * DIM + cc];
        float4 ud = *(const float4*)&uin[(size_t)sd * DIM + cc];
        s0.x += ua.x; s0.y += ua.y; s0.z += ua.z; s0.w += ua.w;
        s1.x += ub.x; s1.y += ub.y; s1.z += ub.z; s1.w += ub.w;
        s2.x += uc.x; s2.y += uc.y; s2.z += uc.z; s2.w += uc.w;
        s3.x += ud.x; s3.y += ud.y; s3.z += ud.z; s3.w += ud.w;
    }
    for (; k < p1; k++) {
        int sa = __ldg(&g_csr[k]);
        float4 ua = *(const float4*)&uin[(size_t)sa * DIM + cc];
        s0.x += ua.x; s0.y += ua.y; s0.z += ua.z; s0.w += ua.w;
    }
    s0.x += s1.x + s2.x + s3.x; s0.y += s1.y + s2.y + s3.y;
    s0.z += s1.z + s2.z + s3.z; s0.w += s1.w + s2.w + s3.w;
    float dp1 = (float)(p1 - p0 + 1);
    float4 z4;
    z4.x = fmaf(scv.x, s0.x, dp1 * shv.x);
    z4.y = fmaf(scv.y, s0.y, dp1 * shv.y);
    z4.z = fmaf(scv.z, s0.z, dp1 * shv.z);
    z4.w = fmaf(scv.w, s0.w, dp1 * shv.w);
    *(float4*)&g_z[(size_t)node * DIM + cc] = z4;

    if (layer > 0) {
        const float lw_prev = __ldg(&lwp[layer - 1]);
        float4 h;
        h.x = fmaf(un.x, scv.x, shv.x); h.y = fmaf(un.y, scv.y, shv.y);
        h.z = fmaf(un.z, scv.z, shv.z); h.w = fmaf(un.w, scv.w, shv.w);
        float4 a;
        if (layer == 1) {
            float lb = __ldg(lbp);
            a = make_float4(lb, lb, lb, lb);
        } else {
            a = *(const float4*)&g_acc[(size_t)node * DIM + cc];
        }
        a.x = fmaf(lw_prev, h.x, a.x); a.y = fmaf(lw_prev, h.y, a.y);
        a.z = fmaf(lw_prev, h.z, a.z); a.w = fmaf(lw_prev, h.w, a.w);
        *(float4*)&g_acc[(size_t)node * DIM + cc] = a;
    }
}

// ---------------- GIN MLP via mma.sync bf16x3 (2x4 warp tiling) -------------
__global__ void __launch_bounds__(256, 1)
gin_mma_kernel(const float* __restrict__ b1, const float* __restrict__ b2,
               int layer, int rd, int sout) {
    extern __shared__ char smem[];
    unsigned* sZh = (unsigned*)(smem + SZ_H);
    unsigned* sZl = (unsigned*)(smem + SZ_L);
    unsigned* sWh = (unsigned*)(smem + SW_H);
    unsigned* sWl = (unsigned*)(smem + SW_L);
    float* sU = (float*)(smem + SU_OFF);
    float* sBias = (float*)(smem + SBIAS);
    const int tid = threadIdx.x;
    const int wid = tid >> 5, lane = tid & 31;
    const int rbase = blockIdx.x * 128;
    const int valid = min(128, N_NODES - rbase);
    const int m0 = (wid >> 2) * 64, n0 = (wid & 3) * 32;

    if (tid < 128) { sBias[tid] = b1[tid]; sBias[128 + tid] = b2[tid]; }

    // Z tile -> bf16 hi/lo pairs
    {
        const float* zb = g_z + (size_t)rbase * DIM;
        for (int i = tid; i < 128 * 32; i += 256) {
            int r = i >> 5, c4 = (i & 31) << 2;
            float4 z = make_float4(0, 0, 0, 0);
            if (r < valid) z = *(const float4*)&zb[r * DIM + c4];
            unsigned hp0, lp0, hp1, lp1;
            split2(z.x, z.y, hp0, lp0);
            split2(z.z, z.w, hp1, lp1);
            int o = r * WPAD + (c4 >> 1);
            sZh[o] = hp0; sZh[o + 1] = hp1;
            sZl[o] = lp0; sZl[o + 1] = lp1;
        }
    }
    // W1 images
    for (int i = tid; i < 128 * 16; i += 256) {
        int row = i >> 4, qq = i & 15;
        *(uint4*)&sWh[row * WPAD + qq * 4] =
            ((const uint4*)&g_wimg[layer][0][0][row * 64])[qq];
        *(uint4*)&sWl[row * WPAD + qq * 4] =
            ((const uint4*)&g_wimg[layer][0][1][row * 64])[qq];
    }
    __syncthreads();

    float d[4][4][4];
    mma_stage<8>(sZh, sZl, sWh, sWl, sBias, d, m0, n0, lane);
    epilogue_rebuild(sZh, sZl, d, m0, n0, lane);
    __syncthreads();

    // W2 images
    for (int i = tid; i < 128 * 16; i += 256) {
        int row = i >> 4, qq = i & 15;
        *(uint4*)&sWh[row * WPAD + qq * 4] =
            ((const uint4*)&g_wimg[layer][1][0][row * 64])[qq];
        *(uint4*)&sWl[row * WPAD + qq * 4] =
            ((const uint4*)&g_wimg[layer][1][1][row * 64])[qq];
    }
    __syncthreads();

    mma_stage<8>(sZh, sZl, sWh, sWl, sBias + 128, d, m0, n0, lane);
    __syncthreads();   // W reads done; region becomes sU
    epilogue_store(sU, d, m0, n0, lane, true);
    __syncthreads();

    // stats + coalesced u store
    if (tid < 128) {
        float s = 0.0f, s2 = 0.0f;
        for (int r = 0; r < valid; r++) {
            float v = sU[r * 132 + tid];
            s += v; s2 += v * v;
        }
        atomicAdd(&g_stats[sout][tid], s);
        atomicAdd(&g_stats[sout][DIM + tid], s2);
    }
    {
        float* __restrict__ uout = g_u[rd ^ 1];
        for (int i = tid; i < 128 * 32; i += 256) {
            int r = i >> 5, c4 = (i & 31) << 2;
            if (r < valid)
                *(float4*)&uout[(size_t)(rbase + r) * DIM + c4] =
                    *(const float4*)&sU[r * 132 + c4];
        }
    }
}

// ---------------- ini embed via mma.sync bf16x3 -----------------------------
// stage 1: K=80 (5 k-steps, X padded), relu; stage 2: K=128, no relu/stats.
__global__ void __launch_bounds__(256, 1)
ini_mma_kernel(const float* __restrict__ x,
               const float* __restrict__ b1, const float* __restrict__ b2) {
    extern __shared__ char smem[];
    unsigned* sZh = (unsigned*)(smem + SZ_H);
    unsigned* sZl = (unsigned*)(smem + SZ_L);
    unsigned* sWh = (unsigned*)(smem + SW_H);
    unsigned* sWl = (unsigned*)(smem + SW_L);
    float* sU = (float*)(smem + SU_OFF);
    float* sBias = (float*)(smem + SBIAS);
    const int tid = threadIdx.x;
    const int wid = tid >> 5, lane = tid & 31;
    const int rbase = blockIdx.x * 128;
    const int valid = min(128, N_NODES - rbase);
    const int m0 = (wid >> 2) * 64, n0 = (wid & 3) * 32;

    if (tid < 128) { sBias[tid] = b1[tid]; sBias[128 + tid] = b2[tid]; }

    // X tile -> bf16 hi/lo pairs (40 k-pairs, pair 39 = cols 78,79 -> x1=0)
    for (int i = tid; i < 128 * 40; i += 256) {
        int r = i / 40, p = i - r * 40;
        int node = rbase + r, c = p << 1;
        float x0 = 0.0f, x1 = 0.0f;
        if (node < N_NODES) {
            const float* xr = x + (size_t)node * N_FEAT;
            if (c < N_FEAT)     x0 = xr[c];
            if (c + 1 < N_FEAT) x1 = xr[c + 1];
        }
        unsigned hp, lp;
        split2(x0, x1, hp, lp);
        sZh[r * WPAD + p] = hp;
        sZl[r * WPAD + p] = lp;
    }
    // W1 images (ini slot)
    for (int i = tid; i < 128 * 16; i += 256) {
        int row = i >> 4, qq = i & 15;
        *(uint4*)&sWh[row * WPAD + qq * 4] =
            ((const uint4*)&g_wimg[N_LAYERS][0][0][row * 64])[qq];
        *(uint4*)&sWl[row * WPAD + qq * 4] =
            ((const uint4*)&g_wimg[N_LAYERS][0][1][row * 64])[qq];
    }
    __syncthreads();

    float d[4][4][4];
    mma_stage<5>(sZh, sZl, sWh, sWl, sBias, d, m0, n0, lane);
    epilogue_rebuild(sZh, sZl, d, m0, n0, lane);
    __syncthreads();

    // W2 images (ini slot)
    for (int i = tid; i < 128 * 16; i += 256) {
        int row = i >> 4, qq = i & 15;
        *(uint4*)&sWh[row * WPAD + qq * 4] =
            ((const uint4*)&g_wimg[N_LAYERS][1][0][row * 64])[qq];
        *(uint4*)&sWl[row * WPAD + qq * 4] =
            ((const uint4*)&g_wimg[N_LAYERS][1][1][row * 64])[qq];
    }
    __syncthreads();

    mma_stage<8>(sZh, sZl, sWh, sWl, sBias + 128, d, m0, n0, lane);
    __syncthreads();
    epilogue_store(sU, d, m0, n0, lane, false);   // no relu on ini output
    __syncthreads();

    float* __restrict__ uout = g_u[0];
    for (int i = tid; i < 128 * 32; i += 256) {
        int r = i >> 5, c4 = (i & 31) << 2;
        if (r < valid)
            *(float4*)&uout[(size_t)(rbase + r) * DIM + c4] =
                *(const float4*)&sU[r * 132 + c4];
    }
}

// ---------------- final: BN(u3) + layer-conv + pool -------------------------
__global__ void final_kernel(const float* __restrict__ gamma,
                             const float* __restrict__ beta,
                             const float* __restrict__ lwp,
                             const int* __restrict__ batch,
                             float* __restrict__ out, int rd) {
    __shared__ float sSc[DIM], sSh[DIM];
    const int tid = threadIdx.x;
    if (tid < DIM) {
        float mean = g_stats[0][tid] * (1.0f / N_NODES);
        float var  = g_stats[0][DIM + tid] * (1.0f / N_NODES) - mean * mean;
        float sc = rsqrtf(var + BN_EPS) * gamma[tid];
        sSc[tid] = sc;
        sSh[tid] = beta[tid] - mean * sc;
    }
    __syncthreads();
    int gw = (blockIdx.x * blockDim.x + tid) >> 5;
    if (gw >= N_NODES) return;
    int lane = tid & 31, c4 = lane << 2;
    float lw3 = __ldg(&lwp[N_LAYERS - 1]);
    float4 u = *(const float4*)&g_u[rd][(size_t)gw * DIM + c4];
    float4 a = *(const float4*)&g_acc[(size_t)gw * DIM + c4];
    float4 h;
    h.x = fmaf(u.x, sSc[c4],     sSh[c4]);
    h.y = fmaf(u.y, sSc[c4 + 1], sSh[c4 + 1]);
    h.z = fmaf(u.z, sSc[c4 + 2], sSh[c4 + 2]);
    h.w = fmaf(u.w, sSc[c4 + 3], sSh[c4 + 3]);
    a.x = fmaf(lw3, h.x, a.x); a.y = fmaf(lw3, h.y, a.y);
    a.z = fmaf(lw3, h.z, a.z); a.w = fmaf(lw3, h.w, a.w);
    int b = __ldg(&batch[gw]);
    float* p = &out[b * DIM + c4];
    asm volatile("red.global.add.v4.f32 [%0], {%1,%2,%3,%4};"
                 :: "l"(p), "f"(a.x), "f"(a.y), "f"(a.z), "f"(a.w) : "memory");
}

// ---------------- launch ----------------------------------------------------
extern "C" void kernel_launch(void* const* d_in, const int* in_sizes, int n_in,
                              void* d_out, int out_size) {
    const float* x     = (const float*)d_in[0];
    const int*   ei    = (const int*)  d_in[1];
    const int*   batch = (const int*)  d_in[2];
    const float* iw1   = (const float*)d_in[3];
    const float* ib1   = (const float*)d_in[4];
    const float* iw2   = (const float*)d_in[5];
    const float* ib2   = (const float*)d_in[6];
    const float* gw1   = (const float*)d_in[7];
    const float* gb1   = (const float*)d_in[8];
    const float* gw2   = (const float*)d_in[9];
    const float* gb2   = (const float*)d_in[10];
    const float* gamma = (const float*)d_in[11];
    const float* beta  = (const float*)d_in[12];
    const float* lw    = (const float*)d_in[13];
    const float* lb    = (const float*)d_in[14];
    float* out = (float*)d_out;

    cudaFuncSetAttribute(gin_mma_kernel,
                         cudaFuncAttributeMaxDynamicSharedMemorySize, SMEM_MMA);
    cudaFuncSetAttribute(ini_mma_kernel,
                         cudaFuncAttributeMaxDynamicSharedMemorySize, SMEM_MMA);

    const int mma_blocks  = (N_NODES + 127) / 128;       // 391
    const int warp_blocks = (N_NODES * 32 + 255) / 256;  // 6250

    init_kernel<<<(N_GRAPHS * DIM + 255) / 256, 256>>>(out);
    count_kernel<<<(N_EDGES + 255) / 256, 256>>>(ei);
    wsplit_kernel<<<(NL1 * 2 * 128 * 64 + 255) / 256, 256>>>(gw1, gw2, iw1, iw2);
    ini_mma_kernel<<<mma_blocks, 256, SMEM_MMA>>>(x, ib1, ib2);
    scan_kernel<<<1, 1024>>>();
    fill_kernel<<<(N_EDGES + 255) / 256, 256>>>(ei);

    for (int l = 0; l < N_LAYERS; l++) {
        const float* gm = gamma + (size_t)(l > 0 ? l - 1 : 0) * DIM;
        const float* bt = beta  + (size_t)(l > 0 ? l - 1 : 0) * DIM;
        gather_kernel<<<warp_blocks, 256>>>(gm, bt, lw, lb, l, l & 1);
        gin_mma_kernel<<<mma_blocks, 256, SMEM_MMA>>>(
            gb1 + (size_t)l * DIM, gb2 + (size_t)l * DIM,
            l, l & 1, (l + 1) & 1);
    }

    final_kernel<<<warp_blocks, 256>>>(gamma + (size_t)(N_LAYERS - 1) * DIM,
                                       beta + (size_t)(N_LAYERS - 1) * DIM,
                                       lw, batch, out, 0);
}

// round 16
// speedup vs baseline: 1.4085x; 1.1280x over previous
#include <cuda_runtime.h>
#include <cuda_bf16.h>
#include <cstdint>

#define N_NODES 50000
#define N_EDGES 600000
#define N_GRAPHS 512
#define DIM 128
#define N_FEAT 78
#define N_LAYERS 4
#define BN_EPS 1e-5f
#define NL1 (N_LAYERS + 1)

// ---------------- scratch (device globals; no allocation allowed) ----------
__device__ float g_u[2][(size_t)N_NODES * DIM];  // ping-pong node features
__device__ float g_z[(size_t)N_NODES * DIM];     // gathered GIN input
__device__ float g_acc[(size_t)N_NODES * DIM];   // layer-conv accumulator
__device__ float g_stats[2][2 * DIM];            // double-buffered BN sums
__device__ int   g_deg[N_NODES];
__device__ int   g_ptr[N_NODES + 1];
__device__ int   g_cur[N_NODES];
__device__ int   g_csr[N_EDGES];                 // src sorted by dst
// W^T bf16 hi/lo pair-packed images; slot N_LAYERS = ini weights
__device__ unsigned g_wimg[NL1][2][2][128 * 64];

// ---------------- bf16 hi/lo split ------------------------------------------
__device__ __forceinline__ void split2(float x0, float x1,
                                       unsigned& hp, unsigned& lp) {
    __nv_bfloat16 h0 = __float2bfloat16(x0);
    __nv_bfloat16 h1 = __float2bfloat16(x1);
    __nv_bfloat162 H; H.x = h0; H.y = h1;
    __nv_bfloat162 L = __floats2bfloat162_rn(x0 - __bfloat162float(h0),
                                             x1 - __bfloat162float(h1));
    hp = *(unsigned*)&H;
    lp = *(unsigned*)&L;
}

// ---------------- warp-level bf16 MMA (baseline PTX, no arch-a) ------------
__device__ __forceinline__ void mma16816(float d[4],
                                         unsigned a0, unsigned a1,
                                         unsigned a2, unsigned a3,
                                         unsigned b0, unsigned b1) {
    asm volatile(
        "mma.sync.aligned.m16n8k16.row.col.f32.bf16.bf16.f32 "
        "{%0,%1,%2,%3}, {%4,%5,%6,%7}, {%8,%9}, {%0,%1,%2,%3};"
        : "+f"(d[0]), "+f"(d[1]), "+f"(d[2]), "+f"(d[3])
        : "r"(a0), "r"(a1), "r"(a2), "r"(a3), "r"(b0), "r"(b1));
}

// smem map (bytes); pair-stride 68 u32 (conflict-free: bank = 4g+q)
// 64-row tile -> 103 KB -> 2 blocks/SM.
#define WPAD 68
#define SZ_H 0                        // 64*68 u32 = 17408 B
#define SZ_L 17408
#define SW_H 34816                    // W images: 128 n-rows, 34816 B each
#define SW_L 69632
#define SU_OFF 34816                  // f32 U tile (64x132) reuses W region
#define SBIAS 104448                  // 256 f32
#define SMEM_MMA 105472

// ---------------- 2x4-warp mma stage: warp (mw,nw) -> m32 x n32 ------------
template <int KSTEPS>
__device__ __forceinline__ void mma_stage(const unsigned* __restrict__ sAh,
                                          const unsigned* __restrict__ sAl,
                                          const unsigned* __restrict__ sWh,
                                          const unsigned* __restrict__ sWl,
                                          const float* __restrict__ bias,
                                          float d[2][4][4],
                                          int m0, int n0, int lane) {
    const int g = lane >> 2, q = lane & 3;
    #pragma unroll
    for (int mt = 0; mt < 2; mt++)
        #pragma unroll
        for (int nt = 0; nt < 4; nt++) {
            float bx = bias[n0 + nt * 8 + q * 2];
            float by = bias[n0 + nt * 8 + q * 2 + 1];
            d[mt][nt][0] = bx; d[mt][nt][1] = by;
            d[mt][nt][2] = bx; d[mt][nt][3] = by;
        }
    #pragma unroll 1
    for (int k0 = 0; k0 < KSTEPS; k0++) {
        const int kp = k0 * 8 + q;
        unsigned ah[2][4], al[2][4];
        #pragma unroll
        for (int mt = 0; mt < 2; mt++) {
            int r0 = (m0 + mt * 16 + g) * WPAD, r1 = r0 + 8 * WPAD;
            ah[mt][0] = sAh[r0 + kp];     ah[mt][1] = sAh[r1 + kp];
            ah[mt][2] = sAh[r0 + kp + 4]; ah[mt][3] = sAh[r1 + kp + 4];
            al[mt][0] = sAl[r0 + kp];     al[mt][1] = sAl[r1 + kp];
            al[mt][2] = sAl[r0 + kp + 4]; al[mt][3] = sAl[r1 + kp + 4];
        }
        unsigned bh[4][2], bl[4][2];
        #pragma unroll
        for (int nt = 0; nt < 4; nt++) {
            int bo = (n0 + nt * 8 + g) * WPAD + kp;
            bh[nt][0] = sWh[bo]; bh[nt][1] = sWh[bo + 4];
            bl[nt][0] = sWl[bo]; bl[nt][1] = sWl[bo + 4];
        }
        #pragma unroll
        for (int mt = 0; mt < 2; mt++)
            #pragma unroll
            for (int nt = 0; nt < 4; nt++) {
                mma16816(d[mt][nt], ah[mt][0], ah[mt][1], ah[mt][2], ah[mt][3],
                         bh[nt][0], bh[nt][1]);
                mma16816(d[mt][nt], ah[mt][0], ah[mt][1], ah[mt][2], ah[mt][3],
                         bl[nt][0], bl[nt][1]);
                mma16816(d[mt][nt], al[mt][0], al[mt][1], al[mt][2], al[mt][3],
                         bh[nt][0], bh[nt][1]);
            }
    }
}

// relu(D) -> rebuild A pairs in sAh/sAl (for next stage)
// CALLER MUST __syncthreads() between the stage-1 mma (Z reads) and this
// (Z writes): A rows are shared across the 4 n-warps of the same m-group.
__device__ __forceinline__ void epilogue_rebuild(unsigned* __restrict__ sAh,
                                                 unsigned* __restrict__ sAl,
                                                 float d[2][4][4],
                                                 int m0, int n0, int lane) {
    const int g = lane >> 2, q = lane & 3;
    #pragma unroll
    for (int mt = 0; mt < 2; mt++)
        #pragma unroll
        for (int nt = 0; nt < 4; nt++) {
            int kp = (n0 >> 1) + nt * 4 + q;
            int r0 = (m0 + mt * 16 + g) * WPAD, r1 = r0 + 8 * WPAD;
            unsigned hp, lp;
            split2(fmaxf(d[mt][nt][0], 0.0f), fmaxf(d[mt][nt][1], 0.0f), hp, lp);
            sAh[r0 + kp] = hp; sAl[r0 + kp] = lp;
            split2(fmaxf(d[mt][nt][2], 0.0f), fmaxf(d[mt][nt][3], 0.0f), hp, lp);
            sAh[r1 + kp] = hp; sAl[r1 + kp] = lp;
        }
}

// D (+relu opt) -> sU [64 x 132 f32]
__device__ __forceinline__ void epilogue_store(float* __restrict__ sU,
                                               float d[2][4][4],
                                               int m0, int n0, int lane,
                                               bool do_relu) {
    const int g = lane >> 2, q = lane & 3;
    #pragma unroll
    for (int mt = 0; mt < 2; mt++)
        #pragma unroll
        for (int nt = 0; nt < 4; nt++) {
            int c = n0 + nt * 8 + q * 2;
            int r0 = m0 + mt * 16 + g, r1 = r0 + 8;
            float v0 = d[mt][nt][0], v1 = d[mt][nt][1];
            float v2 = d[mt][nt][2], v3 = d[mt][nt][3];
            if (do_relu) {
                v0 = fmaxf(v0, 0.0f); v1 = fmaxf(v1, 0.0f);
                v2 = fmaxf(v2, 0.0f); v3 = fmaxf(v3, 0.0f);
            }
            *(float2*)&sU[r0 * 132 + c] = make_float2(v0, v1);
            *(float2*)&sU[r1 * 132 + c] = make_float2(v2, v3);
        }
}

// ---------------- CSR build --------------------------------------------------
__global__ void init_kernel(float* __restrict__ out) {
    int i = blockIdx.x * blockDim.x + threadIdx.x;
    if (i < N_NODES) g_deg[i] = 0;
    if (i < N_GRAPHS * DIM) out[i] = 0.0f;
}

__global__ void count_kernel(const int* __restrict__ ei) {
    int e = blockIdx.x * blockDim.x + threadIdx.x;
    if (e < N_EDGES) atomicAdd(&g_deg[__ldg(&ei[N_EDGES + e])], 1);
}

__global__ void scan_kernel() {
    __shared__ int ssum[1024];
    const int t = threadIdx.x;
    const int CH = (N_NODES + 1023) / 1024;
    const int base = t * CH;
    int sum = 0;
    for (int i = 0; i < CH; i++) {
        int idx = base + i;
        if (idx < N_NODES) sum += g_deg[idx];
    }
    ssum[t] = sum;
    __syncthreads();
    for (int off = 1; off < 1024; off <<= 1) {
        int v = (t >= off) ? ssum[t - off] : 0;
        __syncthreads();
        ssum[t] += v;
        __syncthreads();
    }
    int run = ssum[t] - sum;
    for (int i = 0; i < CH; i++) {
        int idx = base + i;
        if (idx < N_NODES) {
            g_ptr[idx] = run;
            g_cur[idx] = run;
            run += g_deg[idx];
        }
    }
    if (t == 0) g_ptr[N_NODES] = N_EDGES;
}

__global__ void fill_kernel(const int* __restrict__ ei) {
    int e = blockIdx.x * blockDim.x + threadIdx.x;
    if (e >= N_EDGES) return;
    int dst = __ldg(&ei[N_EDGES + e]);
    int pos = atomicAdd(&g_cur[dst], 1);
    g_csr[pos] = __ldg(&ei[e]);
}

// ---------------- W images: W^T bf16 hi/lo, k-pair packed -------------------
__global__ void wsplit_kernel(const float* __restrict__ gw1,
                              const float* __restrict__ gw2,
                              const float* __restrict__ iw1,
                              const float* __restrict__ iw2) {
    int t = blockIdx.x * blockDim.x + threadIdx.x;
    if (t >= NL1 * 2 * 128 * 64) return;
    int kp = t & 63;
    int n  = (t >> 6) & 127;
    int s  = (t >> 13) & 1;
    int l  = t >> 14;
    const float* W;
    int K;
    if (l < N_LAYERS) {
        W = (s ? gw2 : gw1) + (size_t)l * DIM * DIM;
        K = DIM;
    } else {
        W = s ? iw2 : iw1;
        K = s ? DIM : N_FEAT;
    }
    int k = kp << 1;
    float x0 = (k < K)     ? W[(size_t)k * DIM + n]       : 0.0f;
    float x1 = (k + 1 < K) ? W[(size_t)(k + 1) * DIM + n] : 0.0f;
    unsigned hp, lp;
    split2(x0, x1, hp, lp);
    g_wimg[l][s][0][n * 64 + kp] = hp;
    g_wimg[l][s][1][n * 64 + kp] = lp;
}

// ---------------- gather: z = sc*(u+sum u_src)+(deg+1)*sh; acc += lw*h -----
__global__ void __launch_bounds__(256)
gather_kernel(const float* __restrict__ gamma, const float* __restrict__ beta,
              const float* __restrict__ lwp, const float* __restrict__ lbp,
              int layer, int rd) {
    if (blockIdx.x == 0 && threadIdx.x < 2 * DIM)
        g_stats[(layer + 1) & 1][threadIdx.x] = 0.0f;
    int node = (blockIdx.x * blockDim.x + threadIdx.x) >> 5;
    if (node >= N_NODES) return;
    const float* __restrict__ uin = g_u[rd];
    const int lane = threadIdx.x & 31, cc = lane << 2;

    float4 scv = make_float4(1, 1, 1, 1), shv = make_float4(0, 0, 0, 0);
    if (layer > 0) {
        const float* st = g_stats[layer & 1];
        float sc[4], sh[4];
        #pragma unroll
        for (int j = 0; j < 4; j++) {
            float mean = __ldg(&st[cc + j]) * (1.0f / N_NODES);
            float var  = __ldg(&st[DIM + cc + j]) * (1.0f / N_NODES)
                         - mean * mean;
            sc[j] = rsqrtf(var + BN_EPS) * __ldg(&gamma[cc + j]);
            sh[j] = __ldg(&beta[cc + j]) - mean * sc[j];
        }
        scv = make_float4(sc[0], sc[1], sc[2], sc[3]);
        shv = make_float4(sh[0], sh[1], sh[2], sh[3]);
    }

    float4 un = *(const float4*)&uin[(size_t)node * DIM + cc];
    int p0 = __ldg(&g_ptr[node]), p1 = __ldg(&g_ptr[node + 1]);
    float4 s0 = un, s1 = make_float4(0, 0, 0, 0);
    float4 s2 = make_float4(0, 0, 0, 0), s3 = make_float4(0, 0, 0, 0);
    int k = p0;
    for (; k + 4 <= p1; k += 4) {
        int sa = __ldg(&g_csr[k]),      sb = __ldg(&g_csr[k + 1]);
        int sc2 = __ldg(&g_csr[k + 2]), sd = __ldg(&g_csr[k + 3]);
        float4 ua = *(const float4*)&uin[(size_t)sa * DIM + cc];
        float4 ub = *(const float4*)&uin[(size_t)sb * DIM + cc];
        float4 uc = *(const float4*)&uin[(size_t)sc2 * DIM + cc];
        float4 ud = *(const float4*)&uin[(size_t)sd * DIM + cc];
        s0.x += ua.x; s0.y += ua.y; s0.z += ua.z; s0.w += ua.w;
        s1.x += ub.x; s1.y += ub.y; s1.z += ub.z; s1.w += ub.w;
        s2.x += uc.x; s2.y += uc.y; s2.z += uc.z; s2.w += uc.w;
        s3.x += ud.x; s3.y += ud.y; s3.z += ud.z; s3.w += ud.w;
    }
    for (; k < p1; k++) {
        int sa = __ldg(&g_csr[k]);
        float4 ua = *(const float4*)&uin[(size_t)sa * DIM + cc];
        s0.x += ua.x; s0.y += ua.y; s0.z += ua.z; s0.w += ua.w;
    }
    s0.x += s1.x + s2.x + s3.x; s0.y += s1.y + s2.y + s3.y;
    s0.z += s1.z + s2.z + s3.z; s0.w += s1.w + s2.w + s3.w;
    float dp1 = (float)(p1 - p0 + 1);
    float4 z4;
    z4.x = fmaf(scv.x, s0.x, dp1 * shv.x);
    z4.y = fmaf(scv.y, s0.y, dp1 * shv.y);
    z4.z = fmaf(scv.z, s0.z, dp1 * shv.z);
    z4.w = fmaf(scv.w, s0.w, dp1 * shv.w);
    *(float4*)&g_z[(size_t)node * DIM + cc] = z4;

    if (layer > 0) {
        const float lw_prev = __ldg(&lwp[layer - 1]);
        float4 h;
        h.x = fmaf(un.x, scv.x, shv.x); h.y = fmaf(un.y, scv.y, shv.y);
        h.z = fmaf(un.z, scv.z, shv.z); h.w = fmaf(un.w, scv.w, shv.w);
        float4 a;
        if (layer == 1) {
            float lb = __ldg(lbp);
            a = make_float4(lb, lb, lb, lb);
        } else {
            a = *(const float4*)&g_acc[(size_t)node * DIM + cc];
        }
        a.x = fmaf(lw_prev, h.x, a.x); a.y = fmaf(lw_prev, h.y, a.y);
        a.z = fmaf(lw_prev, h.z, a.z); a.w = fmaf(lw_prev, h.w, a.w);
        *(float4*)&g_acc[(size_t)node * DIM + cc] = a;
    }
}

// ---------------- GIN MLP via mma.sync bf16x3 (64-row tile, 2 blk/SM) ------
__global__ void __launch_bounds__(256, 2)
gin_mma_kernel(const float* __restrict__ b1, const float* __restrict__ b2,
               int layer, int rd, int sout) {
    extern __shared__ char smem[];
    unsigned* sZh = (unsigned*)(smem + SZ_H);
    unsigned* sZl = (unsigned*)(smem + SZ_L);
    unsigned* sWh = (unsigned*)(smem + SW_H);
    unsigned* sWl = (unsigned*)(smem + SW_L);
    float* sU = (float*)(smem + SU_OFF);
    float* sBias = (float*)(smem + SBIAS);
    const int tid = threadIdx.x;
    const int wid = tid >> 5, lane = tid & 31;
    const int rbase = blockIdx.x * 64;
    const int valid = min(64, N_NODES - rbase);
    const int m0 = (wid >> 2) * 32, n0 = (wid & 3) * 32;

    if (tid < 128) { sBias[tid] = b1[tid]; sBias[128 + tid] = b2[tid]; }

    // Z tile -> bf16 hi/lo pairs
    {
        const float* zb = g_z + (size_t)rbase * DIM;
        for (int i = tid; i < 64 * 32; i += 256) {
            int r = i >> 5, c4 = (i & 31) << 2;
            float4 z = make_float4(0, 0, 0, 0);
            if (r < valid) z = *(const float4*)&zb[r * DIM + c4];
            unsigned hp0, lp0, hp1, lp1;
            split2(z.x, z.y, hp0, lp0);
            split2(z.z, z.w, hp1, lp1);
            int o = r * WPAD + (c4 >> 1);
            sZh[o] = hp0; sZh[o + 1] = hp1;
            sZl[o] = lp0; sZl[o + 1] = lp1;
        }
    }
    // W1 images
    for (int i = tid; i < 128 * 16; i += 256) {
        int row = i >> 4, qq = i & 15;
        *(uint4*)&sWh[row * WPAD + qq * 4] =
            ((const uint4*)&g_wimg[layer][0][0][row * 64])[qq];
        *(uint4*)&sWl[row * WPAD + qq * 4] =
            ((const uint4*)&g_wimg[layer][0][1][row * 64])[qq];
    }
    __syncthreads();

    float d[2][4][4];
    mma_stage<8>(sZh, sZl, sWh, sWl, sBias, d, m0, n0, lane);
    __syncthreads();           // Z reads complete before rebuild overwrites
    epilogue_rebuild(sZh, sZl, d, m0, n0, lane);
    __syncthreads();

    // W2 images
    for (int i = tid; i < 128 * 16; i += 256) {
        int row = i >> 4, qq = i & 15;
        *(uint4*)&sWh[row * WPAD + qq * 4] =
            ((const uint4*)&g_wimg[layer][1][0][row * 64])[qq];
        *(uint4*)&sWl[row * WPAD + qq * 4] =
            ((const uint4*)&g_wimg[layer][1][1][row * 64])[qq];
    }
    __syncthreads();

    mma_stage<8>(sZh, sZl, sWh, sWl, sBias + 128, d, m0, n0, lane);
    __syncthreads();   // W reads done; region becomes sU
    epilogue_store(sU, d, m0, n0, lane, true);
    __syncthreads();

    // stats + coalesced u store
    if (tid < 128) {
        float s = 0.0f, s2 = 0.0f;
        for (int r = 0; r < valid; r++) {
            float v = sU[r * 132 + tid];
            s += v; s2 += v * v;
        }
        atomicAdd(&g_stats[sout][tid], s);
        atomicAdd(&g_stats[sout][DIM + tid], s2);
    }
    {
        float* __restrict__ uout = g_u[rd ^ 1];
        for (int i = tid; i < 64 * 32; i += 256) {
            int r = i >> 5, c4 = (i & 31) << 2;
            if (r < valid)
                *(float4*)&uout[(size_t)(rbase + r) * DIM + c4] =
                    *(const float4*)&sU[r * 132 + c4];
        }
    }
}

// ---------------- ini embed via mma.sync bf16x3 (64-row tile) ---------------
__global__ void __launch_bounds__(256, 2)
ini_mma_kernel(const float* __restrict__ x,
               const float* __restrict__ b1, const float* __restrict__ b2) {
    extern __shared__ char smem[];
    unsigned* sZh = (unsigned*)(smem + SZ_H);
    unsigned* sZl = (unsigned*)(smem + SZ_L);
    unsigned* sWh = (unsigned*)(smem + SW_H);
    unsigned* sWl = (unsigned*)(smem + SW_L);
    float* sU = (float*)(smem + SU_OFF);
    float* sBias = (float*)(smem + SBIAS);
    const int tid = threadIdx.x;
    const int wid = tid >> 5, lane = tid & 31;
    const int rbase = blockIdx.x * 64;
    const int valid = min(64, N_NODES - rbase);
    const int m0 = (wid >> 2) * 32, n0 = (wid & 3) * 32;

    if (tid < 128) { sBias[tid] = b1[tid]; sBias[128 + tid] = b2[tid]; }

    // X tile -> bf16 hi/lo pairs (40 k-pairs; pair 39 = cols 78,79 -> x1=0)
    for (int i = tid; i < 64 * 40; i += 256) {
        int r = i / 40, p = i - r * 40;
        int node = rbase + r, c = p << 1;
        float x0 = 0.0f, x1 = 0.0f;
        if (node < N_NODES) {
            const float* xr = x + (size_t)node * N_FEAT;
            if (c < N_FEAT)     x0 = xr[c];
            if (c + 1 < N_FEAT) x1 = xr[c + 1];
        }
        unsigned hp, lp;
        split2(x0, x1, hp, lp);
        sZh[r * WPAD + p] = hp;
        sZl[r * WPAD + p] = lp;
    }
    // W1 images (ini slot)
    for (int i = tid; i < 128 * 16; i += 256) {
        int row = i >> 4, qq = i & 15;
        *(uint4*)&sWh[row * WPAD + qq * 4] =
            ((const uint4*)&g_wimg[N_LAYERS][0][0][row * 64])[qq];
        *(uint4*)&sWl[row * WPAD + qq * 4] =
            ((const uint4*)&g_wimg[N_LAYERS][0][1][row * 64])[qq];
    }
    __syncthreads();

    float d[2][4][4];
    mma_stage<5>(sZh, sZl, sWh, sWl, sBias, d, m0, n0, lane);
    __syncthreads();           // X reads complete before rebuild overwrites
    epilogue_rebuild(sZh, sZl, d, m0, n0, lane);
    __syncthreads();

    // W2 images (ini slot)
    for (int i = tid; i < 128 * 16; i += 256) {
        int row = i >> 4, qq = i & 15;
        *(uint4*)&sWh[row * WPAD + qq * 4] =
            ((const uint4*)&g_wimg[N_LAYERS][1][0][row * 64])[qq];
        *(uint4*)&sWl[row * WPAD + qq * 4] =
            ((const uint4*)&g_wimg[N_LAYERS][1][1][row * 64])[qq];
    }
    __syncthreads();

    mma_stage<8>(sZh, sZl, sWh, sWl, sBias + 128, d, m0, n0, lane);
    __syncthreads();
    epilogue_store(sU, d, m0, n0, lane, false);   // no relu on ini output
    __syncthreads();

    float* __restrict__ uout = g_u[0];
    for (int i = tid; i < 64 * 32; i += 256) {
        int r = i >> 5, c4 = (i & 31) << 2;
        if (r < valid)
            *(float4*)&uout[(size_t)(rbase + r) * DIM + c4] =
                *(const float4*)&sU[r * 132 + c4];
    }
}

// ---------------- final: BN(u3) + layer-conv + pool -------------------------
__global__ void final_kernel(const float* __restrict__ gamma,
                             const float* __restrict__ beta,
                             const float* __restrict__ lwp,
                             const int* __restrict__ batch,
                             float* __restrict__ out, int rd) {
    __shared__ float sSc[DIM], sSh[DIM];
    const int tid = threadIdx.x;
    if (tid < DIM) {
        float mean = g_stats[0][tid] * (1.0f / N_NODES);
        float var  = g_stats[0][DIM + tid] * (1.0f / N_NODES) - mean * mean;
        float sc = rsqrtf(var + BN_EPS) * gamma[tid];
        sSc[tid] = sc;
        sSh[tid] = beta[tid] - mean * sc;
    }
    __syncthreads();
    int gw = (blockIdx.x * blockDim.x + tid) >> 5;
    if (gw >= N_NODES) return;
    int lane = tid & 31, c4 = lane << 2;
    float lw3 = __ldg(&lwp[N_LAYERS - 1]);
    float4 u = *(const float4*)&g_u[rd][(size_t)gw * DIM + c4];
    float4 a = *(const float4*)&g_acc[(size_t)gw * DIM + c4];
    float4 h;
    h.x = fmaf(u.x, sSc[c4],     sSh[c4]);
    h.y = fmaf(u.y, sSc[c4 + 1], sSh[c4 + 1]);
    h.z = fmaf(u.z, sSc[c4 + 2], sSh[c4 + 2]);
    h.w = fmaf(u.w, sSc[c4 + 3], sSh[c4 + 3]);
    a.x = fmaf(lw3, h.x, a.x); a.y = fmaf(lw3, h.y, a.y);
    a.z = fmaf(lw3, h.z, a.z); a.w = fmaf(lw3, h.w, a.w);
    int b = __ldg(&batch[gw]);
    float* p = &out[b * DIM + c4];
    asm volatile("red.global.add.v4.f32 [%0], {%1,%2,%3,%4};"
                 :: "l"(p), "f"(a.x), "f"(a.y), "f"(a.z), "f"(a.w) : "memory");
}

// ---------------- launch ----------------------------------------------------
extern "C" void kernel_launch(void* const* d_in, const int* in_sizes, int n_in,
                              void* d_out, int out_size) {
    const float* x     = (const float*)d_in[0];
    const int*   ei    = (const int*)  d_in[1];
    const int*   batch = (const int*)  d_in[2];
    const float* iw1   = (const float*)d_in[3];
    const float* ib1   = (const float*)d_in[4];
    const float* iw2   = (const float*)d_in[5];
    const float* ib2   = (const float*)d_in[6];
    const float* gw1   = (const float*)d_in[7];
    const float* gb1   = (const float*)d_in[8];
    const float* gw2   = (const float*)d_in[9];
    const float* gb2   = (const float*)d_in[10];
    const float* gamma = (const float*)d_in[11];
    const float* beta  = (const float*)d_in[12];
    const float* lw    = (const float*)d_in[13];
    const float* lb    = (const float*)d_in[14];
    float* out = (float*)d_out;

    cudaFuncSetAttribute(gin_mma_kernel,
                         cudaFuncAttributeMaxDynamicSharedMemorySize, SMEM_MMA);
    cudaFuncSetAttribute(ini_mma_kernel,
                         cudaFuncAttributeMaxDynamicSharedMemorySize, SMEM_MMA);

    const int mma_blocks  = (N_NODES + 63) / 64;         // 782
    const int warp_blocks = (N_NODES * 32 + 255) / 256;  // 6250

    init_kernel<<<(N_GRAPHS * DIM + 255) / 256, 256>>>(out);
    count_kernel<<<(N_EDGES + 255) / 256, 256>>>(ei);
    wsplit_kernel<<<(NL1 * 2 * 128 * 64 + 255) / 256, 256>>>(gw1, gw2, iw1, iw2);
    ini_mma_kernel<<<mma_blocks, 256, SMEM_MMA>>>(x, ib1, ib2);
    scan_kernel<<<1, 1024>>>();
    fill_kernel<<<(N_EDGES + 255) / 256, 256>>>(ei);

    for (int l = 0; l < N_LAYERS; l++) {
        const float* gm = gamma + (size_t)(l > 0 ? l - 1 : 0) * DIM;
        const float* bt = beta  + (size_t)(l > 0 ? l - 1 : 0) * DIM;
        gather_kernel<<<warp_blocks, 256>>>(gm, bt, lw, lb, l, l & 1);
        gin_mma_kernel<<<mma_blocks, 256, SMEM_MMA>>>(
            gb1 + (size_t)l * DIM, gb2 + (size_t)l * DIM,
            l, l & 1, (l + 1) & 1);
    }

    final_kernel<<<warp_blocks, 256>>>(gamma + (size_t)(N_LAYERS - 1) * DIM,
                                       beta + (size_t)(N_LAYERS - 1) * DIM,
                                       lw, batch, out, 0);
}

// round 17
// speedup vs baseline: 1.4490x; 1.0288x over previous
#include <cuda_runtime.h>
#include <cuda_bf16.h>
#include <cstdint>

#define N_NODES 50000
#define N_EDGES 600000
#define N_GRAPHS 512
#define DIM 128
#define N_FEAT 78
#define N_LAYERS 4
#define BN_EPS 1e-5f
#define NL1 (N_LAYERS + 1)

// ---------------- scratch (device globals; no allocation allowed) ----------
__device__ float g_u[2][(size_t)N_NODES * DIM];  // ping-pong node features
__device__ float g_z[(size_t)N_NODES * DIM];     // gathered GIN input
__device__ float g_acc[(size_t)N_NODES * DIM];   // layer-conv accumulator
__device__ float g_stats[2][2 * DIM];            // double-buffered BN sums
__device__ int   g_deg[N_NODES];
__device__ int   g_ptr[N_NODES + 1];
__device__ int   g_cur[N_NODES];
__device__ int   g_csr[N_EDGES];                 // src sorted by dst
// W^T bf16 hi/lo pair-packed images; slot N_LAYERS = ini weights
__device__ unsigned g_wimg[NL1][2][2][128 * 64];

// ---------------- bf16 hi/lo split ------------------------------------------
__device__ __forceinline__ void split2(float x0, float x1,
                                       unsigned& hp, unsigned& lp) {
    __nv_bfloat16 h0 = __float2bfloat16(x0);
    __nv_bfloat16 h1 = __float2bfloat16(x1);
    __nv_bfloat162 H; H.x = h0; H.y = h1;
    __nv_bfloat162 L = __floats2bfloat162_rn(x0 - __bfloat162float(h0),
                                             x1 - __bfloat162float(h1));
    hp = *(unsigned*)&H;
    lp = *(unsigned*)&L;
}

// ---------------- warp-level bf16 MMA (baseline PTX, no arch-a) ------------
__device__ __forceinline__ void mma16816(float d[4],
                                         unsigned a0, unsigned a1,
                                         unsigned a2, unsigned a3,
                                         unsigned b0, unsigned b1) {
    asm volatile(
        "mma.sync.aligned.m16n8k16.row.col.f32.bf16.bf16.f32 "
        "{%0,%1,%2,%3}, {%4,%5,%6,%7}, {%8,%9}, {%0,%1,%2,%3};"
        : "+f"(d[0]), "+f"(d[1]), "+f"(d[2]), "+f"(d[3])
        : "r"(a0), "r"(a1), "r"(a2), "r"(a3), "r"(b0), "r"(b1));
}

// smem map (bytes); pair-stride 68 u32 (conflict-free: bank = 4g+q)
// 64-row tile, W in 64-n-row chunks -> ~70.7 KB -> 3 blocks/SM.
#define WPAD 68
#define SZ_H 0                        // 64*68 u32 = 17408 B
#define SZ_L 17408
#define SW_H 34816                    // W chunk images: 64 n-rows, 17408 B each
#define SW_L 52224
#define SU_OFF 34816                  // f32 U tile (64x132=33792 B) reuses W
#define SBIAS 69632                   // 256 f32
#define SMEM_MMA 70656

// ---------------- half-stage: 64 n-rows (chunk ch), warp does 16 of them ---
// d[mt][ch*2+nt]; n0l = local n base in chunk (nw*16); ng = global n base.
template <int KSTEPS>
__device__ __forceinline__ void mma_half(const unsigned* __restrict__ sAh,
                                         const unsigned* __restrict__ sAl,
                                         const unsigned* __restrict__ sWh,
                                         const unsigned* __restrict__ sWl,
                                         const float* __restrict__ bias,
                                         float d[2][4][4],
                                         int m0, int n0l, int ng, int ch,
                                         int lane) {
    const int g = lane >> 2, q = lane & 3;
    #pragma unroll
    for (int mt = 0; mt < 2; mt++)
        #pragma unroll
        for (int nt = 0; nt < 2; nt++) {
            float bx = bias[ng + nt * 8 + q * 2];
            float by = bias[ng + nt * 8 + q * 2 + 1];
            float* dd = d[mt][ch * 2 + nt];
            dd[0] = bx; dd[1] = by; dd[2] = bx; dd[3] = by;
        }
    #pragma unroll 1
    for (int k0 = 0; k0 < KSTEPS; k0++) {
        const int kp = k0 * 8 + q;
        unsigned ah[2][4], al[2][4];
        #pragma unroll
        for (int mt = 0; mt < 2; mt++) {
            int r0 = (m0 + mt * 16 + g) * WPAD, r1 = r0 + 8 * WPAD;
            ah[mt][0] = sAh[r0 + kp];     ah[mt][1] = sAh[r1 + kp];
            ah[mt][2] = sAh[r0 + kp + 4]; ah[mt][3] = sAh[r1 + kp + 4];
            al[mt][0] = sAl[r0 + kp];     al[mt][1] = sAl[r1 + kp];
            al[mt][2] = sAl[r0 + kp + 4]; al[mt][3] = sAl[r1 + kp + 4];
        }
        unsigned bh[2][2], bl[2][2];
        #pragma unroll
        for (int nt = 0; nt < 2; nt++) {
            int bo = (n0l + nt * 8 + g) * WPAD + kp;
            bh[nt][0] = sWh[bo]; bh[nt][1] = sWh[bo + 4];
            bl[nt][0] = sWl[bo]; bl[nt][1] = sWl[bo + 4];
        }
        #pragma unroll
        for (int mt = 0; mt < 2; mt++)
            #pragma unroll
            for (int nt = 0; nt < 2; nt++) {
                float* dd = d[mt][ch * 2 + nt];
                mma16816(dd, ah[mt][0], ah[mt][1], ah[mt][2], ah[mt][3],
                         bh[nt][0], bh[nt][1]);
                mma16816(dd, ah[mt][0], ah[mt][1], ah[mt][2], ah[mt][3],
                         bl[nt][0], bl[nt][1]);
                mma16816(dd, al[mt][0], al[mt][1], al[mt][2], al[mt][3],
                         bh[nt][0], bh[nt][1]);
            }
    }
}

// column index for d[mt][j]: n_j = (j>>1)*64 + nw16 + (j&1)*8
__device__ __forceinline__ int njof(int j, int nw16) {
    return ((j >> 1) << 6) + nw16 + ((j & 1) << 3);
}

// relu(D) -> rebuild A pairs in sAh/sAl.
// CALLER MUST __syncthreads() between the stage-1 mma (Z reads) and this.
__device__ __forceinline__ void epilogue_rebuild(unsigned* __restrict__ sAh,
                                                 unsigned* __restrict__ sAl,
                                                 float d[2][4][4],
                                                 int m0, int nw16, int lane) {
    const int g = lane >> 2, q = lane & 3;
    #pragma unroll
    for (int mt = 0; mt < 2; mt++)
        #pragma unroll
        for (int j = 0; j < 4; j++) {
            int kp = (njof(j, nw16) >> 1) + q;
            int r0 = (m0 + mt * 16 + g) * WPAD, r1 = r0 + 8 * WPAD;
            unsigned hp, lp;
            split2(fmaxf(d[mt][j][0], 0.0f), fmaxf(d[mt][j][1], 0.0f), hp, lp);
            sAh[r0 + kp] = hp; sAl[r0 + kp] = lp;
            split2(fmaxf(d[mt][j][2], 0.0f), fmaxf(d[mt][j][3], 0.0f), hp, lp);
            sAh[r1 + kp] = hp; sAl[r1 + kp] = lp;
        }
}

// D (+relu opt) -> sU [64 x 132 f32]
__device__ __forceinline__ void epilogue_store(float* __restrict__ sU,
                                               float d[2][4][4],
                                               int m0, int nw16, int lane,
                                               bool do_relu) {
    const int g = lane >> 2, q = lane & 3;
    #pragma unroll
    for (int mt = 0; mt < 2; mt++)
        #pragma unroll
        for (int j = 0; j < 4; j++) {
            int c = njof(j, nw16) + q * 2;
            int r0 = m0 + mt * 16 + g, r1 = r0 + 8;
            float v0 = d[mt][j][0], v1 = d[mt][j][1];
            float v2 = d[mt][j][2], v3 = d[mt][j][3];
            if (do_relu) {
                v0 = fmaxf(v0, 0.0f); v1 = fmaxf(v1, 0.0f);
                v2 = fmaxf(v2, 0.0f); v3 = fmaxf(v3, 0.0f);
            }
            *(float2*)&sU[r0 * 132 + c] = make_float2(v0, v1);
            *(float2*)&sU[r1 * 132 + c] = make_float2(v2, v3);
        }
}

// ---------------- CSR build --------------------------------------------------
__global__ void init_kernel(float* __restrict__ out) {
    int i = blockIdx.x * blockDim.x + threadIdx.x;
    if (i < N_NODES) g_deg[i] = 0;
    if (i < N_GRAPHS * DIM) out[i] = 0.0f;
}

__global__ void count_kernel(const int* __restrict__ ei) {
    int e = blockIdx.x * blockDim.x + threadIdx.x;
    if (e < N_EDGES) atomicAdd(&g_deg[__ldg(&ei[N_EDGES + e])], 1);
}

__global__ void scan_kernel() {
    __shared__ int ssum[1024];
    const int t = threadIdx.x;
    const int CH = (N_NODES + 1023) / 1024;
    const int base = t * CH;
    int sum = 0;
    for (int i = 0; i < CH; i++) {
        int idx = base + i;
        if (idx < N_NODES) sum += g_deg[idx];
    }
    ssum[t] = sum;
    __syncthreads();
    for (int off = 1; off < 1024; off <<= 1) {
        int v = (t >= off) ? ssum[t - off] : 0;
        __syncthreads();
        ssum[t] += v;
        __syncthreads();
    }
    int run = ssum[t] - sum;
    for (int i = 0; i < CH; i++) {
        int idx = base + i;
        if (idx < N_NODES) {
            g_ptr[idx] = run;
            g_cur[idx] = run;
            run += g_deg[idx];
        }
    }
    if (t == 0) g_ptr[N_NODES] = N_EDGES;
}

__global__ void fill_kernel(const int* __restrict__ ei) {
    int e = blockIdx.x * blockDim.x + threadIdx.x;
    if (e >= N_EDGES) return;
    int dst = __ldg(&ei[N_EDGES + e]);
    int pos = atomicAdd(&g_cur[dst], 1);
    g_csr[pos] = __ldg(&ei[e]);
}

// ---------------- W images: W^T bf16 hi/lo, k-pair packed -------------------
__global__ void wsplit_kernel(const float* __restrict__ gw1,
                              const float* __restrict__ gw2,
                              const float* __restrict__ iw1,
                              const float* __restrict__ iw2) {
    int t = blockIdx.x * blockDim.x + threadIdx.x;
    if (t >= NL1 * 2 * 128 * 64) return;
    int kp = t & 63;
    int n  = (t >> 6) & 127;
    int s  = (t >> 13) & 1;
    int l  = t >> 14;
    const float* W;
    int K;
    if (l < N_LAYERS) {
        W = (s ? gw2 : gw1) + (size_t)l * DIM * DIM;
        K = DIM;
    } else {
        W = s ? iw2 : iw1;
        K = s ? DIM : N_FEAT;
    }
    int k = kp << 1;
    float x0 = (k < K)     ? W[(size_t)k * DIM + n]       : 0.0f;
    float x1 = (k + 1 < K) ? W[(size_t)(k + 1) * DIM + n] : 0.0f;
    unsigned hp, lp;
    split2(x0, x1, hp, lp);
    g_wimg[l][s][0][n * 64 + kp] = hp;
    g_wimg[l][s][1][n * 64 + kp] = lp;
}

// ---------------- gather: z = sc*(u+sum u_src)+(deg+1)*sh; acc += lw*h -----
__global__ void __launch_bounds__(256)
gather_kernel(const float* __restrict__ gamma, const float* __restrict__ beta,
              const float* __restrict__ lwp, const float* __restrict__ lbp,
              int layer, int rd) {
    if (blockIdx.x == 0 && threadIdx.x < 2 * DIM)
        g_stats[(layer + 1) & 1][threadIdx.x] = 0.0f;
    int node = (blockIdx.x * blockDim.x + threadIdx.x) >> 5;
    if (node >= N_NODES) return;
    const float* __restrict__ uin = g_u[rd];
    const int lane = threadIdx.x & 31, cc = lane << 2;

    float4 scv = make_float4(1, 1, 1, 1), shv = make_float4(0, 0, 0, 0);
    if (layer > 0) {
        const float* st = g_stats[layer & 1];
        float sc[4], sh[4];
        #pragma unroll
        for (int j = 0; j < 4; j++) {
            float mean = __ldg(&st[cc + j]) * (1.0f / N_NODES);
            float var  = __ldg(&st[DIM + cc + j]) * (1.0f / N_NODES)
                         - mean * mean;
            sc[j] = rsqrtf(var + BN_EPS) * __ldg(&gamma[cc + j]);
            sh[j] = __ldg(&beta[cc + j]) - mean * sc[j];
        }
        scv = make_float4(sc[0], sc[1], sc[2], sc[3]);
        shv = make_float4(sh[0], sh[1], sh[2], sh[3]);
    }

    float4 un = *(const float4*)&uin[(size_t)node * DIM + cc];
    int p0 = __ldg(&g_ptr[node]), p1 = __ldg(&g_ptr[node + 1]);
    float4 s0 = un, s1 = make_float4(0, 0, 0, 0);
    float4 s2 = make_float4(0, 0, 0, 0), s3 = make_float4(0, 0, 0, 0);
    int k = p0;
    for (; k + 4 <= p1; k += 4) {
        int sa = __ldg(&g_csr[k]),      sb = __ldg(&g_csr[k + 1]);
        int sc2 = __ldg(&g_csr[k + 2]), sd = __ldg(&g_csr[k + 3]);
        float4 ua = *(const float4*)&uin[(size_t)sa * DIM + cc];
        float4 ub = *(const float4*)&uin[(size_t)sb * DIM + cc];
        float4 uc = *(const float4*)&uin[(size_t)sc2 * DIM + cc];
        float4 ud = *(const float4*)&uin[(size_t)sd * DIM + cc];
        s0.x += ua.x; s0.y += ua.y; s0.z += ua.z; s0.w += ua.w;
        s1.x += ub.x; s1.y += ub.y; s1.z += ub.z; s1.w += ub.w;
        s2.x += uc.x; s2.y += uc.y; s2.z += uc.z; s2.w += uc.w;
        s3.x += ud.x; s3.y += ud.y; s3.z += ud.z; s3.w += ud.w;
    }
    for (; k < p1; k++) {
        int sa = __ldg(&g_csr[k]);
        float4 ua = *(const float4*)&uin[(size_t)sa * DIM + cc];
        s0.x += ua.x; s0.y += ua.y; s0.z += ua.z; s0.w += ua.w;
    }
    s0.x += s1.x + s2.x + s3.x; s0.y += s1.y + s2.y + s3.y;
    s0.z += s1.z + s2.z + s3.z; s0.w += s1.w + s2.w + s3.w;
    float dp1 = (float)(p1 - p0 + 1);
    float4 z4;
    z4.x = fmaf(scv.x, s0.x, dp1 * shv.x);
    z4.y = fmaf(scv.y, s0.y, dp1 * shv.y);
    z4.z = fmaf(scv.z, s0.z, dp1 * shv.z);
    z4.w = fmaf(scv.w, s0.w, dp1 * shv.w);
    *(float4*)&g_z[(size_t)node * DIM + cc] = z4;

    if (layer > 0) {
        const float lw_prev = __ldg(&lwp[layer - 1]);
        float4 h;
        h.x = fmaf(un.x, scv.x, shv.x); h.y = fmaf(un.y, scv.y, shv.y);
        h.z = fmaf(un.z, scv.z, shv.z); h.w = fmaf(un.w, scv.w, shv.w);
        float4 a;
        if (layer == 1) {
            float lb = __ldg(lbp);
            a = make_float4(lb, lb, lb, lb);
        } else {
            a = *(const float4*)&g_acc[(size_t)node * DIM + cc];
        }
        a.x = fmaf(lw_prev, h.x, a.x); a.y = fmaf(lw_prev, h.y, a.y);
        a.z = fmaf(lw_prev, h.z, a.z); a.w = fmaf(lw_prev, h.w, a.w);
        *(float4*)&g_acc[(size_t)node * DIM + cc] = a;
    }
}

// load one 64-n-row W chunk (hi+lo) into smem
__device__ __forceinline__ void load_wchunk(unsigned* __restrict__ sWh,
                                            unsigned* __restrict__ sWl,
                                            const unsigned* __restrict__ wh,
                                            const unsigned* __restrict__ wl,
                                            int ch, int tid) {
    for (int i = tid; i < 64 * 16; i += 256) {
        int row = i >> 4, qq = i & 15;
        *(uint4*)&sWh[row * WPAD + qq * 4] =
            ((const uint4*)&wh[(ch * 64 + row) * 64])[qq];
        *(uint4*)&sWl[row * WPAD + qq * 4] =
            ((const uint4*)&wl[(ch * 64 + row) * 64])[qq];
    }
}

// ---------------- GIN MLP via mma.sync bf16x3 (3 blk/SM, W chunked) --------
__global__ void __launch_bounds__(256, 3)
gin_mma_kernel(const float* __restrict__ b1, const float* __restrict__ b2,
               int layer, int rd, int sout) {
    extern __shared__ char smem[];
    unsigned* sZh = (unsigned*)(smem + SZ_H);
    unsigned* sZl = (unsigned*)(smem + SZ_L);
    unsigned* sWh = (unsigned*)(smem + SW_H);
    unsigned* sWl = (unsigned*)(smem + SW_L);
    float* sU = (float*)(smem + SU_OFF);
    float* sBias = (float*)(smem + SBIAS);
    const int tid = threadIdx.x;
    const int wid = tid >> 5, lane = tid & 31;
    const int rbase = blockIdx.x * 64;
    const int valid = min(64, N_NODES - rbase);
    const int m0 = (wid >> 2) * 32, nw16 = (wid & 3) * 16;
    const unsigned* w1h = &g_wimg[layer][0][0][0];
    const unsigned* w1l = &g_wimg[layer][0][1][0];
    const unsigned* w2h = &g_wimg[layer][1][0][0];
    const unsigned* w2l = &g_wimg[layer][1][1][0];

    if (tid < 128) { sBias[tid] = b1[tid]; sBias[128 + tid] = b2[tid]; }

    // Z tile -> bf16 hi/lo pairs
    {
        const float* zb = g_z + (size_t)rbase * DIM;
        for (int i = tid; i < 64 * 32; i += 256) {
            int r = i >> 5, c4 = (i & 31) << 2;
            float4 z = make_float4(0, 0, 0, 0);
            if (r < valid) z = *(const float4*)&zb[r * DIM + c4];
            unsigned hp0, lp0, hp1, lp1;
            split2(z.x, z.y, hp0, lp0);
            split2(z.z, z.w, hp1, lp1);
            int o = r * WPAD + (c4 >> 1);
            sZh[o] = hp0; sZh[o + 1] = hp1;
            sZl[o] = lp0; sZl[o + 1] = lp1;
        }
    }
    load_wchunk(sWh, sWl, w1h, w1l, 0, tid);
    __syncthreads();

    float d[2][4][4];
    // ---- stage 1 ----
    mma_half<8>(sZh, sZl, sWh, sWl, sBias, d, m0, nw16, nw16, 0, lane);
    __syncthreads();                         // sW reads done
    load_wchunk(sWh, sWl, w1h, w1l, 1, tid);
    __syncthreads();
    mma_half<8>(sZh, sZl, sWh, sWl, sBias, d, m0, nw16, 64 + nw16, 1, lane);
    __syncthreads();                         // Z reads + sW reads done
    epilogue_rebuild(sZh, sZl, d, m0, nw16, lane);
    load_wchunk(sWh, sWl, w2h, w2l, 0, tid);
    __syncthreads();
    // ---- stage 2 ----
    mma_half<8>(sZh, sZl, sWh, sWl, sBias + 128, d, m0, nw16, nw16, 0, lane);
    __syncthreads();
    load_wchunk(sWh, sWl, w2h, w2l, 1, tid);
    __syncthreads();
    mma_half<8>(sZh, sZl, sWh, sWl, sBias + 128, d, m0, nw16, 64 + nw16, 1, lane);
    __syncthreads();                         // W reads done; region becomes sU
    epilogue_store(sU, d, m0, nw16, lane, true);
    __syncthreads();

    // stats + coalesced u store
    if (tid < 128) {
        float s = 0.0f, s2 = 0.0f;
        for (int r = 0; r < valid; r++) {
            float v = sU[r * 132 + tid];
            s += v; s2 += v * v;
        }
        atomicAdd(&g_stats[sout][tid], s);
        atomicAdd(&g_stats[sout][DIM + tid], s2);
    }
    {
        float* __restrict__ uout = g_u[rd ^ 1];
        for (int i = tid; i < 64 * 32; i += 256) {
            int r = i >> 5, c4 = (i & 31) << 2;
            if (r < valid)
                *(float4*)&uout[(size_t)(rbase + r) * DIM + c4] =
                    *(const float4*)&sU[r * 132 + c4];
        }
    }
}

// ---------------- ini embed via mma.sync bf16x3 (3 blk/SM) ------------------
__global__ void __launch_bounds__(256, 3)
ini_mma_kernel(const float* __restrict__ x,
               const float* __restrict__ b1, const float* __restrict__ b2) {
    extern __shared__ char smem[];
    unsigned* sZh = (unsigned*)(smem + SZ_H);
    unsigned* sZl = (unsigned*)(smem + SZ_L);
    unsigned* sWh = (unsigned*)(smem + SW_H);
    unsigned* sWl = (unsigned*)(smem + SW_L);
    float* sU = (float*)(smem + SU_OFF);
    float* sBias = (float*)(smem + SBIAS);
    const int tid = threadIdx.x;
    const int wid = tid >> 5, lane = tid & 31;
    const int rbase = blockIdx.x * 64;
    const int valid = min(64, N_NODES - rbase);
    const int m0 = (wid >> 2) * 32, nw16 = (wid & 3) * 16;
    const unsigned* w1h = &g_wimg[N_LAYERS][0][0][0];
    const unsigned* w1l = &g_wimg[N_LAYERS][0][1][0];
    const unsigned* w2h = &g_wimg[N_LAYERS][1][0][0];
    const unsigned* w2l = &g_wimg[N_LAYERS][1][1][0];

    if (tid < 128) { sBias[tid] = b1[tid]; sBias[128 + tid] = b2[tid]; }

    // X tile -> bf16 hi/lo pairs (40 k-pairs; pair 39 = cols 78,79 -> x1=0)
    for (int i = tid; i < 64 * 40; i += 256) {
        int r = i / 40, p = i - r * 40;
        int node = rbase + r, c = p << 1;
        float x0 = 0.0f, x1 = 0.0f;
        if (node < N_NODES) {
            const float* xr = x + (size_t)node * N_FEAT;
            if (c < N_FEAT)     x0 = xr[c];
            if (c + 1 < N_FEAT) x1 = xr[c + 1];
        }
        unsigned hp, lp;
        split2(x0, x1, hp, lp);
        sZh[r * WPAD + p] = hp;
        sZl[r * WPAD + p] = lp;
    }
    load_wchunk(sWh, sWl, w1h, w1l, 0, tid);
    __syncthreads();

    float d[2][4][4];
    // ---- stage 1 (K = 80 -> 5 k-steps) ----
    mma_half<5>(sZh, sZl, sWh, sWl, sBias, d, m0, nw16, nw16, 0, lane);
    __syncthreads();
    load_wchunk(sWh, sWl, w1h, w1l, 1, tid);
    __syncthreads();
    mma_half<5>(sZh, sZl, sWh, sWl, sBias, d, m0, nw16, 64 + nw16, 1, lane);
    __syncthreads();                         // X reads + sW reads done
    epilogue_rebuild(sZh, sZl, d, m0, nw16, lane);
    load_wchunk(sWh, sWl, w2h, w2l, 0, tid);
    __syncthreads();
    // ---- stage 2 (K = 128) ----
    mma_half<8>(sZh, sZl, sWh, sWl, sBias + 128, d, m0, nw16, nw16, 0, lane);
    __syncthreads();
    load_wchunk(sWh, sWl, w2h, w2l, 1, tid);
    __syncthreads();
    mma_half<8>(sZh, sZl, sWh, sWl, sBias + 128, d, m0, nw16, 64 + nw16, 1, lane);
    __syncthreads();
    epilogue_store(sU, d, m0, nw16, lane, false);   // no relu on ini output
    __syncthreads();

    float* __restrict__ uout = g_u[0];
    for (int i = tid; i < 64 * 32; i += 256) {
        int r = i >> 5, c4 = (i & 31) << 2;
        if (r < valid)
            *(float4*)&uout[(size_t)(rbase + r) * DIM + c4] =
                *(const float4*)&sU[r * 132 + c4];
    }
}

// ---------------- final: BN(u3) + layer-conv + pool -------------------------
__global__ void final_kernel(const float* __restrict__ gamma,
                             const float* __restrict__ beta,
                             const float* __restrict__ lwp,
                             const int* __restrict__ batch,
                             float* __restrict__ out, int rd) {
    __shared__ float sSc[DIM], sSh[DIM];
    const int tid = threadIdx.x;
    if (tid < DIM) {
        float mean = g_stats[0][tid] * (1.0f / N_NODES);
        float var  = g_stats[0][DIM + tid] * (1.0f / N_NODES) - mean * mean;
        float sc = rsqrtf(var + BN_EPS) * gamma[tid];
        sSc[tid] = sc;
        sSh[tid] = beta[tid] - mean * sc;
    }
    __syncthreads();
    int gw = (blockIdx.x * blockDim.x + tid) >> 5;
    if (gw >= N_NODES) return;
    int lane = tid & 31, c4 = lane << 2;
    float lw3 = __ldg(&lwp[N_LAYERS - 1]);
    float4 u = *(const float4*)&g_u[rd][(size_t)gw * DIM + c4];
    float4 a = *(const float4*)&g_acc[(size_t)gw * DIM + c4];
    float4 h;
    h.x = fmaf(u.x, sSc[c4],     sSh[c4]);
    h.y = fmaf(u.y, sSc[c4 + 1], sSh[c4 + 1]);
    h.z = fmaf(u.z, sSc[c4 + 2], sSh[c4 + 2]);
    h.w = fmaf(u.w, sSc[c4 + 3], sSh[c4 + 3]);
    a.x = fmaf(lw3, h.x, a.x); a.y = fmaf(lw3, h.y, a.y);
    a.z = fmaf(lw3, h.z, a.z); a.w = fmaf(lw3, h.w, a.w);
    int b = __ldg(&batch[gw]);
    float* p = &out[b * DIM + c4];
    asm volatile("red.global.add.v4.f32 [%0], {%1,%2,%3,%4};"
                 :: "l"(p), "f"(a.x), "f"(a.y), "f"(a.z), "f"(a.w) : "memory");
}

// ---------------- launch ----------------------------------------------------
extern "C" void kernel_launch(void* const* d_in, const int* in_sizes, int n_in,
                              void* d_out, int out_size) {
    const float* x     = (const float*)d_in[0];
    const int*   ei    = (const int*)  d_in[1];
    const int*   batch = (const int*)  d_in[2];
    const float* iw1   = (const float*)d_in[3];
    const float* ib1   = (const float*)d_in[4];
    const float* iw2   = (const float*)d_in[5];
    const float* ib2   = (const float*)d_in[6];
    const float* gw1   = (const float*)d_in[7];
    const float* gb1   = (const float*)d_in[8];
    const float* gw2   = (const float*)d_in[9];
    const float* gb2   = (const float*)d_in[10];
    const float* gamma = (const float*)d_in[11];
    const float* beta  = (const float*)d_in[12];
    const float* lw    = (const float*)d_in[13];
    const float* lb    = (const float*)d_in[14];
    float* out = (float*)d_out;

    cudaFuncSetAttribute(gin_mma_kernel,
                         cudaFuncAttributeMaxDynamicSharedMemorySize, SMEM_MMA);
    cudaFuncSetAttribute(ini_mma_kernel,
                         cudaFuncAttributeMaxDynamicSharedMemorySize, SMEM_MMA);

    const int mma_blocks  = (N_NODES + 63) / 64;         // 782
    const int warp_blocks = (N_NODES * 32 + 255) / 256;  // 6250

    init_kernel<<<(N_GRAPHS * DIM + 255) / 256, 256>>>(out);
    count_kernel<<<(N_EDGES + 255) / 256, 256>>>(ei);
    wsplit_kernel<<<(NL1 * 2 * 128 * 64 + 255) / 256, 256>>>(gw1, gw2, iw1, iw2);
    ini_mma_kernel<<<mma_blocks, 256, SMEM_MMA>>>(x, ib1, ib2);
    scan_kernel<<<1, 1024>>>();
    fill_kernel<<<(N_EDGES + 255) / 256, 256>>>(ei);

    for (int l = 0; l < N_LAYERS; l++) {
        const float* gm = gamma + (size_t)(l > 0 ? l - 1 : 0) * DIM;
        const float* bt = beta  + (size_t)(l > 0 ? l - 1 : 0) * DIM;
        gather_kernel<<<warp_blocks, 256>>>(gm, bt, lw, lb, l, l & 1);
        gin_mma_kernel<<<mma_blocks, 256, SMEM_MMA>>>(
            gb1 + (size_t)l * DIM, gb2 + (size_t)l * DIM,
            l, l & 1, (l + 1) & 1);
    }

    final_kernel<<<warp_blocks, 256>>>(gamma + (size_t)(N_LAYERS - 1) * DIM,
                                       beta + (size_t)(N_LAYERS - 1) * DIM,
                                       lw, batch, out, 0);
}